// round 10
// baseline (speedup 1.0000x reference)
#include <cuda_runtime.h>
#include <cuda_bf16.h>
#include <cstdint>

// ---------------- problem constants ----------------
#define BATCH 8
#define CIN 512
#define HH 50
#define WW 50
#define NPX (HH*WW)          // 2500
#define NA 9
#define NANCH (NPX*NA)       // 22500
#define PRE_NMS 1000
#define POST_NMS 300
#define NMS_THR 0.7f
#define IMGF 800.0f
#define MIN_SIZE 16.0f

// ---------------- device scratch (static; no allocations allowed) ----------------
__device__ float g_feat[(size_t)BATCH*CIN*NPX];     // shared conv output (relu'd)
__device__ float g_boxes[(size_t)BATCH*NANCH*4];
__device__ unsigned int g_key[(size_t)BATCH*NANCH]; // monotone score key (0 == invalid)

// ---- packed f32x2 helpers (Blackwell 2xFP32 path) ----
__device__ __forceinline__ unsigned long long pk2(float lo, float hi) {
    unsigned long long r;
    asm("mov.b64 %0, {%1, %2};" : "=l"(r) : "f"(lo), "f"(hi));
    return r;
}
__device__ __forceinline__ void fma2(unsigned long long& d, unsigned long long a, unsigned long long b) {
    asm("fma.rn.f32x2 %0, %1, %2, %3;" : "=l"(d) : "l"(a), "l"(b), "l"(d));
}
__device__ __forceinline__ void add2(unsigned long long& d, unsigned long long a) {
    asm("add.rn.f32x2 %0, %1, %2;" : "=l"(d) : "l"(d), "l"(a));
}
__device__ __forceinline__ void upk2(unsigned long long v, float& lo, float& hi) {
    asm("mov.b64 {%0, %1}, %2;" : "=f"(lo), "=f"(hi) : "l"(v));
}

// ============================================================
// Kernel 1: 3x3 conv 512->512, SAME, +bias, ReLU, fp32
// Packed f32x2 FMAs: each 64-bit lane-pair accumulates two outputs;
// per-output scalar FMA sequence over (chunk, c, dy, dx) identical to
// round-3 passing kernel => bitwise identical output.
// block: 256 threads, tile 64 out-ch x (2 rows x 64 cols)
// thread: 4 consecutive k x (2 rows x 4 consecutive cols)
// smem: sIn [2][8][4][68], sW [2][8][9][68]  (same as round-9)
// ============================================================
#define IN_TILE (8*4*68)          // 2176 floats per buffer
#define W_TILE  (8*9*68)          // 4896 floats per buffer
#define CONV_SMEM (2*(IN_TILE + W_TILE)*4)   // 56576 bytes

__global__ __launch_bounds__(256, 2) void conv3x3_kernel(
    const float* __restrict__ x, const float* __restrict__ w, const float* __restrict__ bias)
{
    extern __shared__ float cs[];
    float* sIn = cs;               // buf*IN_TILE + c*272 + r*68 + xx
    float* sW  = cs + 2*IN_TILE;   // buf*W_TILE  + c*612 + q*68 + k

    const int r0 = blockIdx.x * 2;    // output row pair
    const int k0 = blockIdx.y * 64;
    const int b  = blockIdx.z;
    const int tid = threadIdx.x;
    const int kg = tid >> 4;          // 0..15 -> 4 consecutive k
    const int pxg = tid & 15;         // 0..15 -> 4 consecutive cols, 2 rows

    const float* xb = x + (size_t)b * CIN * NPX;
    const float* wk = w + (size_t)k0 * (CIN * 9);

    // ---- precompute input loader offsets (once) ----
    int inoff[9];
#pragma unroll
    for (int t = 0; t < 9; ++t) {
        int idx = tid + 256 * t;
        if (idx < IN_TILE) {
            int c = idx / 272; int rem = idx % 272;
            int r = rem / 68;  int xx = rem % 68;
            int gy = r0 - 1 + r;
            int gx = xx - 1;
            bool ok = (xx < 66) && ((unsigned)gy < (unsigned)HH) && ((unsigned)gx < (unsigned)WW);
            inoff[t] = ok ? (c * NPX + gy * WW + gx) : -1;
        } else inoff[t] = -2;
    }

    auto load_chunk = [&](int ch, int buf) {
        float* dIn = sIn + buf * IN_TILE;
        float* dW  = sW  + buf * W_TILE;
        const int ginc = ch * 8 * NPX;
        const int winc = ch * 72;       // offset within a k-row of w (floats)
#pragma unroll
        for (int t = 0; t < 9; ++t) {
            int o = inoff[t];
            if (o != -2)
                dIn[tid + 256 * t] = (o >= 0) ? xb[ginc + o] : 0.f;
        }
        // weights: 64 k-rows x 72 floats = 1152 float4, coalesced LDG then
        // transpose-scatter into [c][q][68] (k fastest, padded rows)
#pragma unroll
        for (int t = 0; t < 5; ++t) {
            int v4 = tid + 256 * t;
            if (v4 < 1152) {
                int kk = v4 / 18;               // const-divisor
                int f  = v4 - kk * 18;          // float4 index within k-row
                const float4 wv = *(const float4*)&wk[(size_t)kk * (CIN * 9) + winc + f * 4];
                const float vals[4] = {wv.x, wv.y, wv.z, wv.w};
#pragma unroll
                for (int j = 0; j < 4; ++j) {
                    int e = f * 4 + j;          // 0..71 = c*9 + q
                    int c = e / 9;
                    int q = e - c * 9;
                    dW[c * 612 + q * 68 + kk] = vals[j];
                }
            }
        }
    };

    // tot2[jj][ro*2 + p]: packed pair of outputs (cols 4pxg+2p, 4pxg+2p+1)
    unsigned long long tot2[4][4];
#pragma unroll
    for (int jj = 0; jj < 4; ++jj)
#pragma unroll
        for (int t = 0; t < 4; ++t) tot2[jj][t] = 0ull;

    load_chunk(0, 0);
    __syncthreads();

    for (int ch = 0; ch < CIN / 8; ++ch) {
        const int cur = ch & 1;
        if (ch + 1 < CIN / 8) load_chunk(ch + 1, cur ^ 1);

        const float* bIn = sIn + cur * IN_TILE;
        const float* bW  = sW  + cur * W_TILE + kg * 4;   // this thread's 4 k

        unsigned long long acc2[4][4];
#pragma unroll
        for (int jj = 0; jj < 4; ++jj)
#pragma unroll
            for (int t = 0; t < 4; ++t) acc2[jj][t] = 0ull;

#pragma unroll
        for (int c = 0; c < 8; ++c) {
            // load 4 input rows x 6 cols (vectorized, reused across dy/dx)
            float rows[4][6];
#pragma unroll
            for (int r = 0; r < 4; ++r) {
                const float4 v4 = *(const float4*)&bIn[c * 272 + r * 68 + 4 * pxg];
                const float2 v2 = *(const float2*)&bIn[c * 272 + r * 68 + 4 * pxg + 4];
                rows[r][0] = v4.x; rows[r][1] = v4.y; rows[r][2] = v4.z; rows[r][3] = v4.w;
                rows[r][4] = v2.x; rows[r][5] = v2.y;
            }
#pragma unroll
            for (int dy = 0; dy < 3; ++dy) {
#pragma unroll
                for (int dx = 0; dx < 3; ++dx) {
                    const float4 wq = *(const float4*)&bW[c * 612 + (dy * 3 + dx) * 68];
                    unsigned long long wp[4] = {
                        pk2(wq.x, wq.x), pk2(wq.y, wq.y), pk2(wq.z, wq.z), pk2(wq.w, wq.w)
                    };
                    unsigned long long pa[4];
                    pa[0] = pk2(rows[dy    ][dx    ], rows[dy    ][dx + 1]);
                    pa[1] = pk2(rows[dy    ][dx + 2], rows[dy    ][dx + 3]);
                    pa[2] = pk2(rows[dy + 1][dx    ], rows[dy + 1][dx + 1]);
                    pa[3] = pk2(rows[dy + 1][dx + 2], rows[dy + 1][dx + 3]);
#pragma unroll
                    for (int jj = 0; jj < 4; ++jj)
#pragma unroll
                        for (int t = 0; t < 4; ++t)
                            fma2(acc2[jj][t], wp[jj], pa[t]);
                }
            }
        }
#pragma unroll
        for (int jj = 0; jj < 4; ++jj)
#pragma unroll
            for (int t = 0; t < 4; ++t) add2(tot2[jj][t], acc2[jj][t]);

        __syncthreads();
    }

    // epilogue: bias + relu + store
#pragma unroll
    for (int ro = 0; ro < 2; ++ro) {
        int row = r0 + ro;
#pragma unroll
        for (int p = 0; p < 2; ++p) {
#pragma unroll
            for (int jj = 0; jj < 4; ++jj) {
                float v0, v1;
                upk2(tot2[jj][ro * 2 + p], v0, v1);
                int k = k0 + kg * 4 + jj;
                float bb = bias[k];
                int col0 = 4 * pxg + 2 * p;
                if (col0 < WW)
                    g_feat[((size_t)b * CIN + k) * NPX + row * WW + col0] = fmaxf(v0 + bb, 0.f);
                if (col0 + 1 < WW)
                    g_feat[((size_t)b * CIN + k) * NPX + row * WW + col0 + 1] = fmaxf(v1 + bb, 0.f);
            }
        }
    }
}

// ============================================================
// Kernel 2: fused 1x1 heads (cls 18 + reg 36) + anchor decode.
// ============================================================
__global__ __launch_bounds__(256) void heads_decode_kernel(
    const float* __restrict__ wc, const float* __restrict__ bc,
    const float* __restrict__ wr, const float* __restrict__ brg)
{
    extern __shared__ float X[];            // [512][32]
    __shared__ float scls[32 * 18];
    __shared__ float sreg[32 * 36];

    const int b = blockIdx.y;
    const int p0 = blockIdx.x * 32;
    const int tid = threadIdx.x;

    for (int idx = tid; idx < CIN * 32; idx += 256) {
        int c = idx >> 5; int j = idx & 31;
        int p = p0 + j;
        X[idx] = (p < NPX) ? g_feat[((size_t)b * CIN + c) * NPX + p] : 0.f;
    }
    __syncthreads();

    for (int t = tid; t < 54 * 8; t += 256) {
        int o = t >> 3;
        int j0 = (t & 7) * 4;
        float bb = (o < 18) ? bc[o] : brg[o - 18];
        const float* W = (o < 18) ? (wc + (size_t)o * CIN) : (wr + (size_t)(o - 18) * CIN);
        float t0 = 0.f, t1 = 0.f, t2 = 0.f, t3 = 0.f;
        for (int cc = 0; cc < CIN; cc += 8) {
            float a0 = 0.f, a1 = 0.f, a2 = 0.f, a3 = 0.f;
#pragma unroll
            for (int u = 0; u < 8; ++u) {
                int c = cc + u;
                float wv = __ldg(&W[c]);
                const float4 xv = *(const float4*)&X[c * 32 + j0];
                a0 = fmaf(wv, xv.x, a0);
                a1 = fmaf(wv, xv.y, a1);
                a2 = fmaf(wv, xv.z, a2);
                a3 = fmaf(wv, xv.w, a3);
            }
            t0 += a0; t1 += a1; t2 += a2; t3 += a3;
        }
        float accs[4] = {t0 + bb, t1 + bb, t2 + bb, t3 + bb};
#pragma unroll
        for (int jj = 0; jj < 4; ++jj) {
            int j = j0 + jj;
            if (o < 18) scls[j * 18 + o] = accs[jj];
            else        sreg[j * 36 + (o - 18)] = accs[jj];
        }
    }
    __syncthreads();

    // decode 32*9 = 288 anchors
    for (int t = tid; t < 32 * NA; t += 256) {
        int j = t / NA;
        int a = t % NA;
        int p = p0 + j;
        if (p >= NPX) continue;
        int yy = p / WW;
        int xx = p % WW;

        int ri = a / 3, si = a % 3;
        float ratio = (ri == 0) ? 0.5f : (ri == 1 ? 1.0f : 2.0f);
        float scale = (si == 0) ? 8.0f : (si == 1 ? 16.0f : 32.0f);
        float ah = 16.0f * scale * sqrtf(ratio);
        float aw = 16.0f * scale * sqrtf(1.0f / ratio);
        float sy = yy * 16.0f, sx = xx * 16.0f;
        float ay1 = sy + 8.0f - ah * 0.5f;
        float ax1 = sx + 8.0f - aw * 0.5f;
        float ay2 = sy + 8.0f + ah * 0.5f;
        float ax2 = sx + 8.0f + aw * 0.5f;

        float h = ay2 - ay1;
        float w = ax2 - ax1;
        float cy = ay1 + 0.5f * h;
        float cx = ax1 + 0.5f * w;

        const float* rg = &sreg[j * 36 + a * 4];
        float ncy = rg[0] * h + cy;
        float ncx = rg[1] * w + cx;
        float nh = h * expf(rg[2]);
        float nw = w * expf(rg[3]);

        float y1 = fminf(fmaxf(ncy - 0.5f * nh, 0.f), IMGF);
        float x1 = fminf(fmaxf(ncx - 0.5f * nw, 0.f), IMGF);
        float y2 = fminf(fmaxf(ncy + 0.5f * nh, 0.f), IMGF);
        float x2 = fminf(fmaxf(ncx + 0.5f * nw, 0.f), IMGF);

        float hs = y2 - y1, ws = x2 - x1;
        bool valid = (hs >= MIN_SIZE) && (ws >= MIN_SIZE);

        float c0 = scls[j * 18 + a * 2 + 0], c1 = scls[j * 18 + a * 2 + 1];
        float m = fmaxf(c0, c1);
        float e0 = expf(c0 - m);
        float e1 = expf(c1 - m);
        float score = e1 / (e0 + e1);

        int n = p * NA + a;
        float* bx = &g_boxes[((size_t)b * NANCH + n) * 4];
        bx[0] = y1; bx[1] = x1; bx[2] = y2; bx[3] = x2;
        g_key[(size_t)b * NANCH + n] = valid ? (__float_as_uint(score) | 0x80000000u) : 0u;
    }
}

// ============================================================
// Kernel 3: per-image top-1000 select + sort + bitmask NMS + top-300 output
// ============================================================
#define PROP_SMEM 160256

__global__ __launch_bounds__(1024) void propose_kernel(float* __restrict__ out)
{
    extern __shared__ unsigned char smem[];
    unsigned int* skey = (unsigned int*)smem;
    unsigned long long* cand = (unsigned long long*)(smem + 90112);
    float* sb     = (float*)smem;
    float* sarea  = (float*)(smem + 16000);
    float* sscore = (float*)(smem + 20000);
    unsigned int* mask = (unsigned int*)(smem + 24000);
    int* sA = (int*)(smem + 152064);
    int* sB = (int*)(smem + 152064 + 4096);
    __shared__ int s_cnt;
    __shared__ unsigned int s_T;
    __shared__ int s_nc;
    __shared__ int s_NK;
    __shared__ unsigned int kw[32];

    const int b = blockIdx.x;
    const int tid = threadIdx.x;
    const int wid = tid >> 5;
    const int lane = tid & 31;
    const unsigned int* gk = g_key + (size_t)b * NANCH;

    for (int n = tid; n < NANCH; n += 1024) skey[n] = gk[n];
    if (tid == 0) s_T = 0u;
    __syncthreads();

    for (int bit = 31; bit >= 0; --bit) {
        unsigned int T2 = s_T | (1u << bit);
        if (tid == 0) s_cnt = 0;
        __syncthreads();
        int c = 0;
        for (int n = tid; n < NANCH; n += 1024) c += (skey[n] >= T2) ? 1 : 0;
#pragma unroll
        for (int o = 16; o; o >>= 1) c += __shfl_down_sync(0xFFFFFFFFu, c, o);
        if (lane == 0) atomicAdd(&s_cnt, c);
        __syncthreads();
        if (tid == 0 && s_cnt >= PRE_NMS) s_T = T2;
        __syncthreads();
    }
    unsigned int T = s_T;
    if (tid == 0) s_nc = 0;
    __syncthreads();

    for (int n = tid; n < NANCH; n += 1024) {
        unsigned int k = skey[n];
        if (k >= T) {
            int pos = atomicAdd(&s_nc, 1);
            if (pos < 2048)
                cand[pos] = ((unsigned long long)k << 32) | (unsigned int)(~n);
        }
    }
    __syncthreads();
    int nc = min(s_nc, 2048);
    for (int i = tid; i < 2048; i += 1024)
        if (i >= nc) cand[i] = 0ull;
    __syncthreads();

    for (int k = 2; k <= 2048; k <<= 1) {
        for (int j = k >> 1; j > 0; j >>= 1) {
            __syncthreads();
#pragma unroll
            for (int base = 0; base < 2048; base += 1024) {
                int i = base + tid;
                int ixj = i ^ j;
                if (ixj > i) {
                    unsigned long long a = cand[i], c2 = cand[ixj];
                    bool up = ((i & k) == 0);
                    bool swap = up ? (a < c2) : (a > c2);
                    if (swap) { cand[i] = c2; cand[ixj] = a; }
                }
            }
        }
    }
    __syncthreads();

    float myScore = 0.f;
    if (tid < PRE_NMS) {
        unsigned long long ck = cand[tid];
        unsigned int idx = ~(unsigned int)(ck & 0xFFFFFFFFull);
        if (idx >= (unsigned)NANCH) idx = 0;
        const float* bx = g_boxes + ((size_t)b * NANCH + idx) * 4;
        float y1 = bx[0], x1 = bx[1], y2 = bx[2], x2 = bx[3];
        sb[tid * 4 + 0] = y1; sb[tid * 4 + 1] = x1;
        sb[tid * 4 + 2] = y2; sb[tid * 4 + 3] = x2;
        sarea[tid] = (y2 - y1) * (x2 - x1);
        unsigned int kb = (unsigned int)(ck >> 32);
        myScore = __uint_as_float(kb ^ 0x80000000u);
        sscore[tid] = myScore;
    }
    __syncthreads();

    for (int i = wid; i < PRE_NMS; i += 32) {
        const float4 bi = ((const float4*)sb)[i];
        const float ai = sarea[i];
#pragma unroll 4
        for (int w0 = 0; w0 < 32; ++w0) {
            int j = w0 * 32 + lane;
            bool sup = false;
            if (j > i && j < PRE_NMS) {
                const float4 bj = ((const float4*)sb)[j];
                float ty = fmaxf(bi.x, bj.x);
                float tx = fmaxf(bi.y, bj.y);
                float by = fminf(bi.z, bj.z);
                float bxx = fminf(bi.w, bj.w);
                float ih = fmaxf(by - ty, 0.f);
                float iw = fmaxf(bxx - tx, 0.f);
                float inter = ih * iw;
                float iou = inter / (ai + sarea[j] - inter + 1e-9f);
                sup = iou > NMS_THR;
            }
            unsigned int word = __ballot_sync(0xFFFFFFFFu, sup);
            if (lane == 0) mask[i * 32 + w0] = word;
        }
    }
    if (tid < 32) kw[tid] = 0xFFFFFFFFu;
    __syncthreads();

    if (tid < 32) {
        for (int i = 0; i < PRE_NMS; ++i) {
            unsigned int w = kw[i >> 5];
            if ((w >> (i & 31)) & 1u)
                kw[tid] &= ~mask[i * 32 + tid];
            __syncwarp();
        }
    }
    __syncthreads();

    int keepv = (tid < PRE_NMS) ? (int)((kw[tid >> 5] >> (tid & 31)) & 1u) : 0;
    sA[tid] = keepv;
    __syncthreads();
    int* src = sA; int* dst = sB;
    for (int d = 1; d < 1024; d <<= 1) {
        int v = src[tid];
        if (tid >= d) v += src[tid - d];
        dst[tid] = v;
        __syncthreads();
        int* t = src; src = dst; dst = t;
    }
    if (tid == 0) s_NK = src[PRE_NMS - 1];
    __syncthreads();
    int NK = s_NK;

    float* ob = out + (size_t)b * POST_NMS * 5;
    if (tid < PRE_NMS) {
        int incl = src[tid];
        int excl = incl - keepv;
        int slot; float sc;
        if (keepv) { slot = excl; sc = myScore; }
        else       { slot = NK + (tid - excl); sc = -1e30f; }
        if (slot < POST_NMS) {
            ob[slot * 5 + 0] = sb[tid * 4 + 0];
            ob[slot * 5 + 1] = sb[tid * 4 + 1];
            ob[slot * 5 + 2] = sb[tid * 4 + 2];
            ob[slot * 5 + 3] = sb[tid * 4 + 3];
            ob[slot * 5 + 4] = sc;
        }
    }
}

// ============================================================
extern "C" void kernel_launch(void* const* d_in, const int* in_sizes, int n_in,
                              void* d_out, int out_size)
{
    const float* x       = (const float*)d_in[0];
    const float* w_share = (const float*)d_in[1];
    const float* b_share = (const float*)d_in[2];
    const float* w_cls   = (const float*)d_in[3];
    const float* b_cls   = (const float*)d_in[4];
    const float* w_reg   = (const float*)d_in[5];
    const float* b_reg   = (const float*)d_in[6];
    float* out = (float*)d_out;

    cudaFuncSetAttribute(conv3x3_kernel, cudaFuncAttributeMaxDynamicSharedMemorySize, CONV_SMEM);
    cudaFuncSetAttribute(heads_decode_kernel, cudaFuncAttributeMaxDynamicSharedMemorySize, CIN * 32 * 4);
    cudaFuncSetAttribute(propose_kernel, cudaFuncAttributeMaxDynamicSharedMemorySize, PROP_SMEM);

    conv3x3_kernel<<<dim3(HH / 2, CIN / 64, BATCH), 256, CONV_SMEM>>>(x, w_share, b_share);
    heads_decode_kernel<<<dim3((NPX + 31) / 32, BATCH), 256, CIN * 32 * 4>>>(w_cls, b_cls, w_reg, b_reg);
    propose_kernel<<<BATCH, 1024, PROP_SMEM>>>(out);
}

// round 11
// speedup vs baseline: 1.0994x; 1.0994x over previous
#include <cuda_runtime.h>
#include <cuda_bf16.h>
#include <cstdint>

// ---------------- problem constants ----------------
#define BATCH 8
#define CIN 512
#define HH 50
#define WW 50
#define NPX (HH*WW)          // 2500
#define NA 9
#define NANCH (NPX*NA)       // 22500
#define PRE_NMS 1000
#define POST_NMS 300
#define NMS_THR 0.7f
#define IMGF 800.0f
#define MIN_SIZE 16.0f

// ---------------- device scratch (static; no allocations allowed) ----------------
__device__ float g_feat[(size_t)BATCH*CIN*NPX];     // shared conv output (relu'd)
__device__ float g_boxes[(size_t)BATCH*NANCH*4];
__device__ unsigned int g_key[(size_t)BATCH*NANCH]; // monotone score key (0 == invalid)

// ---- cp.async helpers ----
__device__ __forceinline__ void cpa4(unsigned int dst, const void* src) {
    asm volatile("cp.async.ca.shared.global [%0], [%1], 4;" :: "r"(dst), "l"(src));
}
__device__ __forceinline__ void cp_commit() {
    asm volatile("cp.async.commit_group;");
}
__device__ __forceinline__ void cp_wait0() {
    asm volatile("cp.async.wait_group 0;");
}

// ============================================================
// Kernel 1: 3x3 conv 512->512, SAME, +bias, ReLU, fp32
// Scalar FMA mainloop (R9 form); loader converted to cp.async direct
// to smem (no register staging). FMA sequence over (chunk, c, dy, dx)
// identical to round-3 passing kernel => bitwise identical output.
// block: 256 threads, tile 64 out-ch x (2 rows x 64 cols)
// thread: 4 consecutive k x (2 rows x 4 consecutive cols)
// smem: sIn [2][8][4][68], sW [2][8][9][68]
// ============================================================
#define IN_TILE (8*4*68)          // 2176 floats per buffer
#define W_TILE  (8*9*68)          // 4896 floats per buffer
#define CONV_SMEM (2*(IN_TILE + W_TILE)*4)   // 56576 bytes

__global__ __launch_bounds__(256, 2) void conv3x3_kernel(
    const float* __restrict__ x, const float* __restrict__ w, const float* __restrict__ bias)
{
    extern __shared__ float cs[];
    float* sIn = cs;               // buf*IN_TILE + c*272 + r*68 + xx
    float* sW  = cs + 2*IN_TILE;   // buf*W_TILE  + c*612 + q*68 + k
    const unsigned int sbase = (unsigned int)__cvta_generic_to_shared(cs);

    const int r0 = blockIdx.x * 2;    // output row pair
    const int k0 = blockIdx.y * 64;
    const int b  = blockIdx.z;
    const int tid = threadIdx.x;
    const int kg = tid >> 4;          // 0..15 -> 4 consecutive k
    const int pxg = tid & 15;         // 0..15 -> 4 consecutive cols, 2 rows

    const float* xb = x + (size_t)b * CIN * NPX;
    const float* wk = w + (size_t)k0 * (CIN * 9);

    // ---- precompute input loader offsets (once) ----
    int inoff[9];
#pragma unroll
    for (int t = 0; t < 9; ++t) {
        int idx = tid + 256 * t;
        if (idx < IN_TILE) {
            int c = idx / 272; int rem = idx % 272;
            int r = rem / 68;  int xx = rem % 68;
            int gy = r0 - 1 + r;
            int gx = xx - 1;
            bool ok = (xx < 66) && ((unsigned)gy < (unsigned)HH) && ((unsigned)gx < (unsigned)WW);
            inoff[t] = ok ? (c * NPX + gy * WW + gx) : -1;
        } else inoff[t] = -2;
    }

    // zero OOB input slots once (positions are chunk-invariant; cp.async
    // loads skip them, so the zeros persist in both buffers)
#pragma unroll
    for (int t = 0; t < 9; ++t) {
        if (inoff[t] == -1) {
            sIn[0 * IN_TILE + tid + 256 * t] = 0.f;
            sIn[1 * IN_TILE + tid + 256 * t] = 0.f;
        }
    }

    auto load_chunk = [&](int ch, int buf) {
        const int ginc = ch * 8 * NPX;
        const int winc = ch * 72;       // offset within a k-row of w (floats)
        const unsigned int dInB = sbase + (unsigned int)(buf * IN_TILE) * 4u;
        const unsigned int dWB  = sbase + (unsigned int)(2 * IN_TILE + buf * W_TILE) * 4u;
#pragma unroll
        for (int t = 0; t < 9; ++t) {
            int o = inoff[t];
            if (o >= 0)
                cpa4(dInB + (unsigned int)(tid + 256 * t) * 4u, xb + ginc + o);
        }
        // weights: 64 k-rows x 72 floats; transpose-scatter into [c][q][68]
#pragma unroll
        for (int t = 0; t < 5; ++t) {
            int v4 = tid + 256 * t;
            if (v4 < 1152) {
                int kk = v4 / 18;               // const-divisor
                int f  = v4 - kk * 18;          // float4 index within k-row
                const float* src = &wk[(size_t)kk * (CIN * 9) + winc + f * 4];
#pragma unroll
                for (int j = 0; j < 4; ++j) {
                    int e = f * 4 + j;          // 0..71 = c*9 + q
                    int c = e / 9;
                    int q = e - c * 9;
                    cpa4(dWB + (unsigned int)(c * 612 + q * 68 + kk) * 4u, src + j);
                }
            }
        }
    };

    float tot[4][8];
#pragma unroll
    for (int jj = 0; jj < 4; ++jj)
#pragma unroll
        for (int i = 0; i < 8; ++i) tot[jj][i] = 0.f;

    load_chunk(0, 0);
    cp_commit();
    cp_wait0();
    __syncthreads();

    for (int ch = 0; ch < CIN / 8; ++ch) {
        const int cur = ch & 1;
        const bool more = (ch + 1 < CIN / 8);
        if (more) { load_chunk(ch + 1, cur ^ 1); cp_commit(); }

        const float* bIn = sIn + cur * IN_TILE;
        const float* bW  = sW  + cur * W_TILE + kg * 4;   // this thread's 4 k

        float acc[4][8];
#pragma unroll
        for (int jj = 0; jj < 4; ++jj)
#pragma unroll
            for (int i = 0; i < 8; ++i) acc[jj][i] = 0.f;

#pragma unroll
        for (int c = 0; c < 8; ++c) {
            // load 4 input rows x 6 cols (vectorized, reused across dy/dx)
            float rows[4][6];
#pragma unroll
            for (int r = 0; r < 4; ++r) {
                const float4 v4 = *(const float4*)&bIn[c * 272 + r * 68 + 4 * pxg];
                const float2 v2 = *(const float2*)&bIn[c * 272 + r * 68 + 4 * pxg + 4];
                rows[r][0] = v4.x; rows[r][1] = v4.y; rows[r][2] = v4.z; rows[r][3] = v4.w;
                rows[r][4] = v2.x; rows[r][5] = v2.y;
            }
#pragma unroll
            for (int dy = 0; dy < 3; ++dy) {
#pragma unroll
                for (int dx = 0; dx < 3; ++dx) {
                    const float4 wq = *(const float4*)&bW[c * 612 + (dy * 3 + dx) * 68];
                    const float wv[4] = {wq.x, wq.y, wq.z, wq.w};
#pragma unroll
                    for (int jj = 0; jj < 4; ++jj)
#pragma unroll
                        for (int ro = 0; ro < 2; ++ro)
#pragma unroll
                            for (int u = 0; u < 4; ++u)
                                acc[jj][ro * 4 + u] =
                                    fmaf(wv[jj], rows[ro + dy][u + dx], acc[jj][ro * 4 + u]);
                }
            }
        }
#pragma unroll
        for (int jj = 0; jj < 4; ++jj)
#pragma unroll
            for (int i = 0; i < 8; ++i) tot[jj][i] += acc[jj][i];

        if (more) cp_wait0();
        __syncthreads();
    }

    // epilogue: bias + relu + store
#pragma unroll
    for (int ro = 0; ro < 2; ++ro) {
        int row = r0 + ro;
#pragma unroll
        for (int u = 0; u < 4; ++u) {
            int col = 4 * pxg + u;
            if (col < WW) {
#pragma unroll
                for (int jj = 0; jj < 4; ++jj) {
                    int k = k0 + kg * 4 + jj;
                    float v = tot[jj][ro * 4 + u] + bias[k];
                    v = fmaxf(v, 0.f);
                    g_feat[((size_t)b * CIN + k) * NPX + row * WW + col] = v;
                }
            }
        }
    }
}

// ============================================================
// Kernel 2: fused 1x1 heads (cls 18 + reg 36) + anchor decode.
// ============================================================
__global__ __launch_bounds__(256) void heads_decode_kernel(
    const float* __restrict__ wc, const float* __restrict__ bc,
    const float* __restrict__ wr, const float* __restrict__ brg)
{
    extern __shared__ float X[];            // [512][32]
    __shared__ float scls[32 * 18];
    __shared__ float sreg[32 * 36];

    const int b = blockIdx.y;
    const int p0 = blockIdx.x * 32;
    const int tid = threadIdx.x;

    for (int idx = tid; idx < CIN * 32; idx += 256) {
        int c = idx >> 5; int j = idx & 31;
        int p = p0 + j;
        X[idx] = (p < NPX) ? g_feat[((size_t)b * CIN + c) * NPX + p] : 0.f;
    }
    __syncthreads();

    for (int t = tid; t < 54 * 8; t += 256) {
        int o = t >> 3;
        int j0 = (t & 7) * 4;
        float bb = (o < 18) ? bc[o] : brg[o - 18];
        const float* W = (o < 18) ? (wc + (size_t)o * CIN) : (wr + (size_t)(o - 18) * CIN);
        float t0 = 0.f, t1 = 0.f, t2 = 0.f, t3 = 0.f;
        for (int cc = 0; cc < CIN; cc += 8) {
            float a0 = 0.f, a1 = 0.f, a2 = 0.f, a3 = 0.f;
#pragma unroll
            for (int u = 0; u < 8; ++u) {
                int c = cc + u;
                float wv = __ldg(&W[c]);
                const float4 xv = *(const float4*)&X[c * 32 + j0];
                a0 = fmaf(wv, xv.x, a0);
                a1 = fmaf(wv, xv.y, a1);
                a2 = fmaf(wv, xv.z, a2);
                a3 = fmaf(wv, xv.w, a3);
            }
            t0 += a0; t1 += a1; t2 += a2; t3 += a3;
        }
        float accs[4] = {t0 + bb, t1 + bb, t2 + bb, t3 + bb};
#pragma unroll
        for (int jj = 0; jj < 4; ++jj) {
            int j = j0 + jj;
            if (o < 18) scls[j * 18 + o] = accs[jj];
            else        sreg[j * 36 + (o - 18)] = accs[jj];
        }
    }
    __syncthreads();

    // decode 32*9 = 288 anchors
    for (int t = tid; t < 32 * NA; t += 256) {
        int j = t / NA;
        int a = t % NA;
        int p = p0 + j;
        if (p >= NPX) continue;
        int yy = p / WW;
        int xx = p % WW;

        int ri = a / 3, si = a % 3;
        float ratio = (ri == 0) ? 0.5f : (ri == 1 ? 1.0f : 2.0f);
        float scale = (si == 0) ? 8.0f : (si == 1 ? 16.0f : 32.0f);
        float ah = 16.0f * scale * sqrtf(ratio);
        float aw = 16.0f * scale * sqrtf(1.0f / ratio);
        float sy = yy * 16.0f, sx = xx * 16.0f;
        float ay1 = sy + 8.0f - ah * 0.5f;
        float ax1 = sx + 8.0f - aw * 0.5f;
        float ay2 = sy + 8.0f + ah * 0.5f;
        float ax2 = sx + 8.0f + aw * 0.5f;

        float h = ay2 - ay1;
        float w = ax2 - ax1;
        float cy = ay1 + 0.5f * h;
        float cx = ax1 + 0.5f * w;

        const float* rg = &sreg[j * 36 + a * 4];
        float ncy = rg[0] * h + cy;
        float ncx = rg[1] * w + cx;
        float nh = h * expf(rg[2]);
        float nw = w * expf(rg[3]);

        float y1 = fminf(fmaxf(ncy - 0.5f * nh, 0.f), IMGF);
        float x1 = fminf(fmaxf(ncx - 0.5f * nw, 0.f), IMGF);
        float y2 = fminf(fmaxf(ncy + 0.5f * nh, 0.f), IMGF);
        float x2 = fminf(fmaxf(ncx + 0.5f * nw, 0.f), IMGF);

        float hs = y2 - y1, ws = x2 - x1;
        bool valid = (hs >= MIN_SIZE) && (ws >= MIN_SIZE);

        float c0 = scls[j * 18 + a * 2 + 0], c1 = scls[j * 18 + a * 2 + 1];
        float m = fmaxf(c0, c1);
        float e0 = expf(c0 - m);
        float e1 = expf(c1 - m);
        float score = e1 / (e0 + e1);

        int n = p * NA + a;
        float* bx = &g_boxes[((size_t)b * NANCH + n) * 4];
        bx[0] = y1; bx[1] = x1; bx[2] = y2; bx[3] = x2;
        g_key[(size_t)b * NANCH + n] = valid ? (__float_as_uint(score) | 0x80000000u) : 0u;
    }
}

// ============================================================
// Kernel 3: per-image top-1000 select + sort + bitmask NMS + top-300 output
// ============================================================
#define PROP_SMEM 160256

__global__ __launch_bounds__(1024) void propose_kernel(float* __restrict__ out)
{
    extern __shared__ unsigned char smem[];
    unsigned int* skey = (unsigned int*)smem;
    unsigned long long* cand = (unsigned long long*)(smem + 90112);
    float* sb     = (float*)smem;
    float* sarea  = (float*)(smem + 16000);
    float* sscore = (float*)(smem + 20000);
    unsigned int* mask = (unsigned int*)(smem + 24000);
    int* sA = (int*)(smem + 152064);
    int* sB = (int*)(smem + 152064 + 4096);
    __shared__ int s_cnt;
    __shared__ unsigned int s_T;
    __shared__ int s_nc;
    __shared__ int s_NK;
    __shared__ unsigned int kw[32];

    const int b = blockIdx.x;
    const int tid = threadIdx.x;
    const int wid = tid >> 5;
    const int lane = tid & 31;
    const unsigned int* gk = g_key + (size_t)b * NANCH;

    for (int n = tid; n < NANCH; n += 1024) skey[n] = gk[n];
    if (tid == 0) s_T = 0u;
    __syncthreads();

    for (int bit = 31; bit >= 0; --bit) {
        unsigned int T2 = s_T | (1u << bit);
        if (tid == 0) s_cnt = 0;
        __syncthreads();
        int c = 0;
        for (int n = tid; n < NANCH; n += 1024) c += (skey[n] >= T2) ? 1 : 0;
#pragma unroll
        for (int o = 16; o; o >>= 1) c += __shfl_down_sync(0xFFFFFFFFu, c, o);
        if (lane == 0) atomicAdd(&s_cnt, c);
        __syncthreads();
        if (tid == 0 && s_cnt >= PRE_NMS) s_T = T2;
        __syncthreads();
    }
    unsigned int T = s_T;
    if (tid == 0) s_nc = 0;
    __syncthreads();

    for (int n = tid; n < NANCH; n += 1024) {
        unsigned int k = skey[n];
        if (k >= T) {
            int pos = atomicAdd(&s_nc, 1);
            if (pos < 2048)
                cand[pos] = ((unsigned long long)k << 32) | (unsigned int)(~n);
        }
    }
    __syncthreads();
    int nc = min(s_nc, 2048);
    for (int i = tid; i < 2048; i += 1024)
        if (i >= nc) cand[i] = 0ull;
    __syncthreads();

    for (int k = 2; k <= 2048; k <<= 1) {
        for (int j = k >> 1; j > 0; j >>= 1) {
            __syncthreads();
#pragma unroll
            for (int base = 0; base < 2048; base += 1024) {
                int i = base + tid;
                int ixj = i ^ j;
                if (ixj > i) {
                    unsigned long long a = cand[i], c2 = cand[ixj];
                    bool up = ((i & k) == 0);
                    bool swap = up ? (a < c2) : (a > c2);
                    if (swap) { cand[i] = c2; cand[ixj] = a; }
                }
            }
        }
    }
    __syncthreads();

    float myScore = 0.f;
    if (tid < PRE_NMS) {
        unsigned long long ck = cand[tid];
        unsigned int idx = ~(unsigned int)(ck & 0xFFFFFFFFull);
        if (idx >= (unsigned)NANCH) idx = 0;
        const float* bx = g_boxes + ((size_t)b * NANCH + idx) * 4;
        float y1 = bx[0], x1 = bx[1], y2 = bx[2], x2 = bx[3];
        sb[tid * 4 + 0] = y1; sb[tid * 4 + 1] = x1;
        sb[tid * 4 + 2] = y2; sb[tid * 4 + 3] = x2;
        sarea[tid] = (y2 - y1) * (x2 - x1);
        unsigned int kb = (unsigned int)(ck >> 32);
        myScore = __uint_as_float(kb ^ 0x80000000u);
        sscore[tid] = myScore;
    }
    __syncthreads();

    for (int i = wid; i < PRE_NMS; i += 32) {
        const float4 bi = ((const float4*)sb)[i];
        const float ai = sarea[i];
#pragma unroll 4
        for (int w0 = 0; w0 < 32; ++w0) {
            int j = w0 * 32 + lane;
            bool sup = false;
            if (j > i && j < PRE_NMS) {
                const float4 bj = ((const float4*)sb)[j];
                float ty = fmaxf(bi.x, bj.x);
                float tx = fmaxf(bi.y, bj.y);
                float by = fminf(bi.z, bj.z);
                float bxx = fminf(bi.w, bj.w);
                float ih = fmaxf(by - ty, 0.f);
                float iw = fmaxf(bxx - tx, 0.f);
                float inter = ih * iw;
                float iou = inter / (ai + sarea[j] - inter + 1e-9f);
                sup = iou > NMS_THR;
            }
            unsigned int word = __ballot_sync(0xFFFFFFFFu, sup);
            if (lane == 0) mask[i * 32 + w0] = word;
        }
    }
    if (tid < 32) kw[tid] = 0xFFFFFFFFu;
    __syncthreads();

    if (tid < 32) {
        for (int i = 0; i < PRE_NMS; ++i) {
            unsigned int w = kw[i >> 5];
            if ((w >> (i & 31)) & 1u)
                kw[tid] &= ~mask[i * 32 + tid];
            __syncwarp();
        }
    }
    __syncthreads();

    int keepv = (tid < PRE_NMS) ? (int)((kw[tid >> 5] >> (tid & 31)) & 1u) : 0;
    sA[tid] = keepv;
    __syncthreads();
    int* src = sA; int* dst = sB;
    for (int d = 1; d < 1024; d <<= 1) {
        int v = src[tid];
        if (tid >= d) v += src[tid - d];
        dst[tid] = v;
        __syncthreads();
        int* t = src; src = dst; dst = t;
    }
    if (tid == 0) s_NK = src[PRE_NMS - 1];
    __syncthreads();
    int NK = s_NK;

    float* ob = out + (size_t)b * POST_NMS * 5;
    if (tid < PRE_NMS) {
        int incl = src[tid];
        int excl = incl - keepv;
        int slot; float sc;
        if (keepv) { slot = excl; sc = myScore; }
        else       { slot = NK + (tid - excl); sc = -1e30f; }
        if (slot < POST_NMS) {
            ob[slot * 5 + 0] = sb[tid * 4 + 0];
            ob[slot * 5 + 1] = sb[tid * 4 + 1];
            ob[slot * 5 + 2] = sb[tid * 4 + 2];
            ob[slot * 5 + 3] = sb[tid * 4 + 3];
            ob[slot * 5 + 4] = sc;
        }
    }
}

// ============================================================
extern "C" void kernel_launch(void* const* d_in, const int* in_sizes, int n_in,
                              void* d_out, int out_size)
{
    const float* x       = (const float*)d_in[0];
    const float* w_share = (const float*)d_in[1];
    const float* b_share = (const float*)d_in[2];
    const float* w_cls   = (const float*)d_in[3];
    const float* b_cls   = (const float*)d_in[4];
    const float* w_reg   = (const float*)d_in[5];
    const float* b_reg   = (const float*)d_in[6];
    float* out = (float*)d_out;

    cudaFuncSetAttribute(conv3x3_kernel, cudaFuncAttributeMaxDynamicSharedMemorySize, CONV_SMEM);
    cudaFuncSetAttribute(heads_decode_kernel, cudaFuncAttributeMaxDynamicSharedMemorySize, CIN * 32 * 4);
    cudaFuncSetAttribute(propose_kernel, cudaFuncAttributeMaxDynamicSharedMemorySize, PROP_SMEM);

    conv3x3_kernel<<<dim3(HH / 2, CIN / 64, BATCH), 256, CONV_SMEM>>>(x, w_share, b_share);
    heads_decode_kernel<<<dim3((NPX + 31) / 32, BATCH), 256, CIN * 32 * 4>>>(w_cls, b_cls, w_reg, b_reg);
    propose_kernel<<<BATCH, 1024, PROP_SMEM>>>(out);
}

// round 13
// speedup vs baseline: 1.1455x; 1.0420x over previous
#include <cuda_runtime.h>
#include <cuda_bf16.h>
#include <cstdint>

// ---------------- problem constants ----------------
#define BATCH 8
#define CIN 512
#define HH 50
#define WW 50
#define NPX (HH*WW)          // 2500
#define NA 9
#define NANCH (NPX*NA)       // 22500
#define PRE_NMS 1000
#define POST_NMS 300
#define NMS_THR 0.7f
#define IMGF 800.0f
#define MIN_SIZE 16.0f

#define PADW 52
#define PADH 56
#define PFLAT (PADW*PADH)    // 2912

// ---------------- device scratch (static; no allocations allowed) ----------------
__device__ float g_feat[(size_t)BATCH*CIN*NPX];     // shared conv output (relu'd)
__device__ float g_boxes[(size_t)BATCH*NANCH*4];
__device__ unsigned int g_key[(size_t)BATCH*NANCH]; // monotone score key (0 == invalid)
__device__ float g_pad_hi[(size_t)BATCH*CIN*PFLAT]; // padded input, tf32-high part
__device__ float g_pad_lo[(size_t)BATCH*CIN*PFLAT]; // tf32(residual)

// ---- helpers ----
__device__ __forceinline__ float tf32r(float x) {
    unsigned int u;
    asm("cvt.rna.tf32.f32 %0, %1;" : "=r"(u) : "f"(x));
    return __uint_as_float(u);
}

// m16n8k8 TF32 MMA (Ampere-class, PTX sm_80+; compiles for plain compute_100)
__device__ __forceinline__ void mma8(float (&d)[4], const uint32_t (&a)[4], const uint32_t (&b)[2]) {
    asm volatile(
        "mma.sync.aligned.m16n8k8.row.col.f32.tf32.tf32.f32 "
        "{%0,%1,%2,%3}, {%4,%5,%6,%7}, {%8,%9}, {%0,%1,%2,%3};"
        : "+f"(d[0]), "+f"(d[1]), "+f"(d[2]), "+f"(d[3])
        : "r"(a[0]), "r"(a[1]), "r"(a[2]), "r"(a[3]), "r"(b[0]), "r"(b[1]));
}

// ============================================================
// Kernel 0: build zero-padded input (52-wide flat) + tf32 hi/lo split
// ============================================================
__global__ void prep_pad_kernel(const float* __restrict__ x)
{
    int idx = blockIdx.x * blockDim.x + threadIdx.x;
    const int total = BATCH * CIN * PFLAT;
    if (idx >= total) return;
    int f = idx % PFLAT;
    int bc = idx / PFLAT;
    int yy = f / PADW, xx = f % PADW;
    float v = 0.f;
    if (yy >= 1 && yy <= HH && xx >= 1 && xx <= WW)
        v = x[(size_t)bc * NPX + (yy - 1) * WW + (xx - 1)];
    float hi = tf32r(v);
    g_pad_hi[idx] = hi;
    g_pad_lo[idx] = tf32r(v - hi);
}

// ============================================================
// Kernel 1: 3x3 conv via mma.sync TF32 split-precision implicit GEMM
// CTA: 256 thr = 8 warps (4 M x 2 N); tile 128 px x 64 kout
// K loop: 16 chunks of 32 ch x 9 taps x 4 k-steps(8) x 3 splits
// smem: winh[32][248], winl[32][248], wraw[64][292]  (bank-conflict-free)
// ============================================================
#define WSTR 248
#define WRSTR 292
#define CONVMMA_SMEM ((2*32*WSTR + 64*WRSTR)*4)   // 138240 bytes

__global__ __launch_bounds__(256) void conv_mma_kernel(
    const float* __restrict__ w, const float* __restrict__ bias)
{
    extern __shared__ float s[];
    float* winh = s;                 // [32][248]
    float* winl = s + 32 * WSTR;     // [32][248]
    float* wraw = s + 64 * WSTR;     // [64][292]

    const int tid = threadIdx.x;
    const int wid = tid >> 5;
    const int lane = tid & 31;
    const int l4 = lane & 3;
    const int lg = lane >> 2;
    const int wm = wid & 3;          // m-tile (32 px)
    const int wn = wid >> 2;         // n-tile (32 kout)

    const int o0 = blockIdx.x * 128;
    const int k0 = blockIdx.y * 64;
    const int b  = blockIdx.z;

    const float* wk = w + (size_t)k0 * (CIN * 9);
    const size_t pbase = (size_t)b * CIN * PFLAT;

    float tot[2][4][4];
#pragma unroll
    for (int i = 0; i < 2; ++i)
#pragma unroll
        for (int j = 0; j < 4; ++j)
#pragma unroll
            for (int r = 0; r < 4; ++r) tot[i][j][r] = 0.f;

    for (int chunk = 0; chunk < 16; ++chunk) {
        const int c0 = chunk * 32;

        // ---- stage chunk ----
        for (int idx = tid; idx < 32 * 234; idx += 256) {
            int c = idx / 234, j = idx - c * 234;
            size_t g = pbase + (size_t)(c0 + c) * PFLAT + o0 + j;
            winh[c * WSTR + j] = g_pad_hi[g];
            winl[c * WSTR + j] = g_pad_lo[g];
        }
        for (int idx = tid; idx < 64 * 288; idx += 256) {
            int k = idx / 288, r = idx - k * 288;
            wraw[k * WRSTR + r] = wk[(size_t)k * (CIN * 9) + c0 * 9 + r];
        }
        __syncthreads();

        float dch[2][4][4];
#pragma unroll
        for (int i = 0; i < 2; ++i)
#pragma unroll
            for (int j = 0; j < 4; ++j)
#pragma unroll
                for (int r = 0; r < 4; ++r) dch[i][j][r] = 0.f;

        for (int q = 0; q < 9; ++q) {
            const int sq = (q / 3) * PADW + (q - (q / 3) * 3);
#pragma unroll
            for (int cs = 0; cs < 4; ++cs) {
                const int cc = cs * 8;

                // B fragments: n = wn*32 + j*8 + lg ; k-cols cc+l4, cc+l4+4
                uint32_t bhi[4][2], blo[4][2];
#pragma unroll
                for (int j = 0; j < 4; ++j) {
                    int n = wn * 32 + j * 8 + lg;
                    float r0 = wraw[n * WRSTR + (cc + l4) * 9 + q];
                    float r1 = wraw[n * WRSTR + (cc + l4 + 4) * 9 + q];
                    float h0 = tf32r(r0), h1 = tf32r(r1);
                    bhi[j][0] = __float_as_uint(h0);
                    bhi[j][1] = __float_as_uint(h1);
                    blo[j][0] = __float_as_uint(tf32r(r0 - h0));
                    blo[j][1] = __float_as_uint(tf32r(r1 - h1));
                }
                // A fragments: rows m0, m0+8 ; k-cols cc+l4, cc+l4+4
                uint32_t ahi[2][4], alo[2][4];
#pragma unroll
                for (int i = 0; i < 2; ++i) {
                    int m0 = wm * 32 + i * 16 + lg;
                    int b0 = (cc + l4) * WSTR + m0 + sq;
                    int b1 = (cc + l4 + 4) * WSTR + m0 + sq;
                    ahi[i][0] = __float_as_uint(winh[b0]);
                    ahi[i][1] = __float_as_uint(winh[b0 + 8]);
                    ahi[i][2] = __float_as_uint(winh[b1]);
                    ahi[i][3] = __float_as_uint(winh[b1 + 8]);
                    alo[i][0] = __float_as_uint(winl[b0]);
                    alo[i][1] = __float_as_uint(winl[b0 + 8]);
                    alo[i][2] = __float_as_uint(winl[b1]);
                    alo[i][3] = __float_as_uint(winl[b1 + 8]);
                }
                // 3 splits
#pragma unroll
                for (int i = 0; i < 2; ++i)
#pragma unroll
                    for (int j = 0; j < 4; ++j) mma8(dch[i][j], ahi[i], bhi[j]);
#pragma unroll
                for (int i = 0; i < 2; ++i)
#pragma unroll
                    for (int j = 0; j < 4; ++j) mma8(dch[i][j], alo[i], bhi[j]);
#pragma unroll
                for (int i = 0; i < 2; ++i)
#pragma unroll
                    for (int j = 0; j < 4; ++j) mma8(dch[i][j], ahi[i], blo[j]);
            }
        }
        __syncthreads();

#pragma unroll
        for (int i = 0; i < 2; ++i)
#pragma unroll
            for (int j = 0; j < 4; ++j)
#pragma unroll
                for (int r = 0; r < 4; ++r) tot[i][j][r] += dch[i][j][r];
    }

    // ---- epilogue: bias + relu + store (D layout: d0 row,c ; d1 row,c+1 ; d2 row+8,c ; d3 row+8,c+1)
    const size_t bbase = (size_t)b * CIN * NPX;
#pragma unroll
    for (int i = 0; i < 2; ++i) {
#pragma unroll
        for (int j = 0; j < 4; ++j) {
            int nb = k0 + wn * 32 + j * 8 + l4 * 2;
            float bv0 = bias[nb], bv1 = bias[nb + 1];
            int o = o0 + wm * 32 + i * 16 + lg;
            {
                int y = o / PADW, xcol = o - y * PADW;
                if (y < HH && xcol < WW) {
                    int px = y * WW + xcol;
                    g_feat[bbase + (size_t)nb * NPX + px]       = fmaxf(tot[i][j][0] + bv0, 0.f);
                    g_feat[bbase + (size_t)(nb + 1) * NPX + px] = fmaxf(tot[i][j][1] + bv1, 0.f);
                }
            }
            {
                int o2 = o + 8;
                int y = o2 / PADW, xcol = o2 - y * PADW;
                if (y < HH && xcol < WW) {
                    int px = y * WW + xcol;
                    g_feat[bbase + (size_t)nb * NPX + px]       = fmaxf(tot[i][j][2] + bv0, 0.f);
                    g_feat[bbase + (size_t)(nb + 1) * NPX + px] = fmaxf(tot[i][j][3] + bv1, 0.f);
                }
            }
        }
    }
}

// ============================================================
// Kernel 2: fused 1x1 heads (cls 18 + reg 36) + anchor decode. (unchanged)
// ============================================================
__global__ __launch_bounds__(256) void heads_decode_kernel(
    const float* __restrict__ wc, const float* __restrict__ bc,
    const float* __restrict__ wr, const float* __restrict__ brg)
{
    extern __shared__ float X[];            // [512][32]
    __shared__ float scls[32 * 18];
    __shared__ float sreg[32 * 36];

    const int b = blockIdx.y;
    const int p0 = blockIdx.x * 32;
    const int tid = threadIdx.x;

    for (int idx = tid; idx < CIN * 32; idx += 256) {
        int c = idx >> 5; int j = idx & 31;
        int p = p0 + j;
        X[idx] = (p < NPX) ? g_feat[((size_t)b * CIN + c) * NPX + p] : 0.f;
    }
    __syncthreads();

    for (int t = tid; t < 54 * 8; t += 256) {
        int o = t >> 3;
        int j0 = (t & 7) * 4;
        float bb = (o < 18) ? bc[o] : brg[o - 18];
        const float* W = (o < 18) ? (wc + (size_t)o * CIN) : (wr + (size_t)(o - 18) * CIN);
        float t0 = 0.f, t1 = 0.f, t2 = 0.f, t3 = 0.f;
        for (int cc = 0; cc < CIN; cc += 8) {
            float a0 = 0.f, a1 = 0.f, a2 = 0.f, a3 = 0.f;
#pragma unroll
            for (int u = 0; u < 8; ++u) {
                int c = cc + u;
                float wv = __ldg(&W[c]);
                const float4 xv = *(const float4*)&X[c * 32 + j0];
                a0 = fmaf(wv, xv.x, a0);
                a1 = fmaf(wv, xv.y, a1);
                a2 = fmaf(wv, xv.z, a2);
                a3 = fmaf(wv, xv.w, a3);
            }
            t0 += a0; t1 += a1; t2 += a2; t3 += a3;
        }
        float accs[4] = {t0 + bb, t1 + bb, t2 + bb, t3 + bb};
#pragma unroll
        for (int jj = 0; jj < 4; ++jj) {
            int j = j0 + jj;
            if (o < 18) scls[j * 18 + o] = accs[jj];
            else        sreg[j * 36 + (o - 18)] = accs[jj];
        }
    }
    __syncthreads();

    for (int t = tid; t < 32 * NA; t += 256) {
        int j = t / NA;
        int a = t % NA;
        int p = p0 + j;
        if (p >= NPX) continue;
        int yy = p / WW;
        int xx = p % WW;

        int ri = a / 3, si = a % 3;
        float ratio = (ri == 0) ? 0.5f : (ri == 1 ? 1.0f : 2.0f);
        float scale = (si == 0) ? 8.0f : (si == 1 ? 16.0f : 32.0f);
        float ah = 16.0f * scale * sqrtf(ratio);
        float aw = 16.0f * scale * sqrtf(1.0f / ratio);
        float sy = yy * 16.0f, sx = xx * 16.0f;
        float ay1 = sy + 8.0f - ah * 0.5f;
        float ax1 = sx + 8.0f - aw * 0.5f;
        float ay2 = sy + 8.0f + ah * 0.5f;
        float ax2 = sx + 8.0f + aw * 0.5f;

        float h = ay2 - ay1;
        float w = ax2 - ax1;
        float cy = ay1 + 0.5f * h;
        float cx = ax1 + 0.5f * w;

        const float* rg = &sreg[j * 36 + a * 4];
        float ncy = rg[0] * h + cy;
        float ncx = rg[1] * w + cx;
        float nh = h * expf(rg[2]);
        float nw = w * expf(rg[3]);

        float y1 = fminf(fmaxf(ncy - 0.5f * nh, 0.f), IMGF);
        float x1 = fminf(fmaxf(ncx - 0.5f * nw, 0.f), IMGF);
        float y2 = fminf(fmaxf(ncy + 0.5f * nh, 0.f), IMGF);
        float x2 = fminf(fmaxf(ncx + 0.5f * nw, 0.f), IMGF);

        float hs = y2 - y1, ws = x2 - x1;
        bool valid = (hs >= MIN_SIZE) && (ws >= MIN_SIZE);

        float c0 = scls[j * 18 + a * 2 + 0], c1 = scls[j * 18 + a * 2 + 1];
        float m = fmaxf(c0, c1);
        float e0 = expf(c0 - m);
        float e1 = expf(c1 - m);
        float score = e1 / (e0 + e1);

        int n = p * NA + a;
        float* bx = &g_boxes[((size_t)b * NANCH + n) * 4];
        bx[0] = y1; bx[1] = x1; bx[2] = y2; bx[3] = x2;
        g_key[(size_t)b * NANCH + n] = valid ? (__float_as_uint(score) | 0x80000000u) : 0u;
    }
}

// ============================================================
// Kernel 3: per-image top-1000 select + sort + bitmask NMS + top-300 output (unchanged)
// ============================================================
#define PROP_SMEM 160256

__global__ __launch_bounds__(1024) void propose_kernel(float* __restrict__ out)
{
    extern __shared__ unsigned char smem[];
    unsigned int* skey = (unsigned int*)smem;
    unsigned long long* cand = (unsigned long long*)(smem + 90112);
    float* sb     = (float*)smem;
    float* sarea  = (float*)(smem + 16000);
    float* sscore = (float*)(smem + 20000);
    unsigned int* mask = (unsigned int*)(smem + 24000);
    int* sA = (int*)(smem + 152064);
    int* sB = (int*)(smem + 152064 + 4096);
    __shared__ int s_cnt;
    __shared__ unsigned int s_T;
    __shared__ int s_nc;
    __shared__ int s_NK;
    __shared__ unsigned int kw[32];

    const int b = blockIdx.x;
    const int tid = threadIdx.x;
    const int wid = tid >> 5;
    const int lane = tid & 31;
    const unsigned int* gk = g_key + (size_t)b * NANCH;

    for (int n = tid; n < NANCH; n += 1024) skey[n] = gk[n];
    if (tid == 0) s_T = 0u;
    __syncthreads();

    for (int bit = 31; bit >= 0; --bit) {
        unsigned int T2 = s_T | (1u << bit);
        if (tid == 0) s_cnt = 0;
        __syncthreads();
        int c = 0;
        for (int n = tid; n < NANCH; n += 1024) c += (skey[n] >= T2) ? 1 : 0;
#pragma unroll
        for (int o = 16; o; o >>= 1) c += __shfl_down_sync(0xFFFFFFFFu, c, o);
        if (lane == 0) atomicAdd(&s_cnt, c);
        __syncthreads();
        if (tid == 0 && s_cnt >= PRE_NMS) s_T = T2;
        __syncthreads();
    }
    unsigned int T = s_T;
    if (tid == 0) s_nc = 0;
    __syncthreads();

    for (int n = tid; n < NANCH; n += 1024) {
        unsigned int k = skey[n];
        if (k >= T) {
            int pos = atomicAdd(&s_nc, 1);
            if (pos < 2048)
                cand[pos] = ((unsigned long long)k << 32) | (unsigned int)(~n);
        }
    }
    __syncthreads();
    int nc = min(s_nc, 2048);
    for (int i = tid; i < 2048; i += 1024)
        if (i >= nc) cand[i] = 0ull;
    __syncthreads();

    for (int k = 2; k <= 2048; k <<= 1) {
        for (int j = k >> 1; j > 0; j >>= 1) {
            __syncthreads();
#pragma unroll
            for (int base = 0; base < 2048; base += 1024) {
                int i = base + tid;
                int ixj = i ^ j;
                if (ixj > i) {
                    unsigned long long a = cand[i], c2 = cand[ixj];
                    bool up = ((i & k) == 0);
                    bool swap = up ? (a < c2) : (a > c2);
                    if (swap) { cand[i] = c2; cand[ixj] = a; }
                }
            }
        }
    }
    __syncthreads();

    float myScore = 0.f;
    if (tid < PRE_NMS) {
        unsigned long long ck = cand[tid];
        unsigned int idx = ~(unsigned int)(ck & 0xFFFFFFFFull);
        if (idx >= (unsigned)NANCH) idx = 0;
        const float* bx = g_boxes + ((size_t)b * NANCH + idx) * 4;
        float y1 = bx[0], x1 = bx[1], y2 = bx[2], x2 = bx[3];
        sb[tid * 4 + 0] = y1; sb[tid * 4 + 1] = x1;
        sb[tid * 4 + 2] = y2; sb[tid * 4 + 3] = x2;
        sarea[tid] = (y2 - y1) * (x2 - x1);
        unsigned int kb = (unsigned int)(ck >> 32);
        myScore = __uint_as_float(kb ^ 0x80000000u);
        sscore[tid] = myScore;
    }
    __syncthreads();

    for (int i = wid; i < PRE_NMS; i += 32) {
        const float4 bi = ((const float4*)sb)[i];
        const float ai = sarea[i];
#pragma unroll 4
        for (int w0 = 0; w0 < 32; ++w0) {
            int j = w0 * 32 + lane;
            bool sup = false;
            if (j > i && j < PRE_NMS) {
                const float4 bj = ((const float4*)sb)[j];
                float ty = fmaxf(bi.x, bj.x);
                float tx = fmaxf(bi.y, bj.y);
                float by = fminf(bi.z, bj.z);
                float bxx = fminf(bi.w, bj.w);
                float ih = fmaxf(by - ty, 0.f);
                float iw = fmaxf(bxx - tx, 0.f);
                float inter = ih * iw;
                float iou = inter / (ai + sarea[j] - inter + 1e-9f);
                sup = iou > NMS_THR;
            }
            unsigned int word = __ballot_sync(0xFFFFFFFFu, sup);
            if (lane == 0) mask[i * 32 + w0] = word;
        }
    }
    if (tid < 32) kw[tid] = 0xFFFFFFFFu;
    __syncthreads();

    if (tid < 32) {
        for (int i = 0; i < PRE_NMS; ++i) {
            unsigned int w = kw[i >> 5];
            if ((w >> (i & 31)) & 1u)
                kw[tid] &= ~mask[i * 32 + tid];
            __syncwarp();
        }
    }
    __syncthreads();

    int keepv = (tid < PRE_NMS) ? (int)((kw[tid >> 5] >> (tid & 31)) & 1u) : 0;
    sA[tid] = keepv;
    __syncthreads();
    int* src = sA; int* dst = sB;
    for (int d = 1; d < 1024; d <<= 1) {
        int v = src[tid];
        if (tid >= d) v += src[tid - d];
        dst[tid] = v;
        __syncthreads();
        int* t = src; src = dst; dst = t;
    }
    if (tid == 0) s_NK = src[PRE_NMS - 1];
    __syncthreads();
    int NK = s_NK;

    float* ob = out + (size_t)b * POST_NMS * 5;
    if (tid < PRE_NMS) {
        int incl = src[tid];
        int excl = incl - keepv;
        int slot; float sc;
        if (keepv) { slot = excl; sc = myScore; }
        else       { slot = NK + (tid - excl); sc = -1e30f; }
        if (slot < POST_NMS) {
            ob[slot * 5 + 0] = sb[tid * 4 + 0];
            ob[slot * 5 + 1] = sb[tid * 4 + 1];
            ob[slot * 5 + 2] = sb[tid * 4 + 2];
            ob[slot * 5 + 3] = sb[tid * 4 + 3];
            ob[slot * 5 + 4] = sc;
        }
    }
}

// ============================================================
extern "C" void kernel_launch(void* const* d_in, const int* in_sizes, int n_in,
                              void* d_out, int out_size)
{
    const float* x       = (const float*)d_in[0];
    const float* w_share = (const float*)d_in[1];
    const float* b_share = (const float*)d_in[2];
    const float* w_cls   = (const float*)d_in[3];
    const float* b_cls   = (const float*)d_in[4];
    const float* w_reg   = (const float*)d_in[5];
    const float* b_reg   = (const float*)d_in[6];
    float* out = (float*)d_out;

    cudaFuncSetAttribute(conv_mma_kernel, cudaFuncAttributeMaxDynamicSharedMemorySize, CONVMMA_SMEM);
    cudaFuncSetAttribute(heads_decode_kernel, cudaFuncAttributeMaxDynamicSharedMemorySize, CIN * 32 * 4);
    cudaFuncSetAttribute(propose_kernel, cudaFuncAttributeMaxDynamicSharedMemorySize, PROP_SMEM);

    const int prep_total = BATCH * CIN * PFLAT;
    prep_pad_kernel<<<(prep_total + 255) / 256, 256>>>(x);
    conv_mma_kernel<<<dim3(21, 8, BATCH), 256, CONVMMA_SMEM>>>(w_share, b_share);
    heads_decode_kernel<<<dim3((NPX + 31) / 32, BATCH), 256, CIN * 32 * 4>>>(w_cls, b_cls, w_reg, b_reg);
    propose_kernel<<<BATCH, 1024, PROP_SMEM>>>(out);
}

// round 15
// speedup vs baseline: 1.1978x; 1.0456x over previous
#include <cuda_runtime.h>
#include <cuda_bf16.h>
#include <cstdint>

// ---------------- problem constants ----------------
#define BATCH 8
#define CIN 512
#define HH 50
#define WW 50
#define NPX (HH*WW)          // 2500
#define NA 9
#define NANCH (NPX*NA)       // 22500
#define PRE_NMS 1000
#define POST_NMS 300
#define NMS_THR 0.7f
#define IMGF 800.0f
#define MIN_SIZE 16.0f

#define PADW 52
#define PADH 56
#define PFLAT (PADW*PADH)    // 2912

#define KSPLIT 256           // kout [0,KSPLIT) -> tensor path, [KSPLIT,512) -> ffma path
#define MMA_BLKS 84          // 21 o-tiles x 4 k-slices
#define FMA_BLKS 100         // 25 row-pairs x 4 k-slices

// ---------------- device scratch (static; no allocations allowed) ----------------
__device__ float g_feat[(size_t)BATCH*CIN*NPX];
__device__ float g_boxes[(size_t)BATCH*NANCH*4];
__device__ unsigned int g_key[(size_t)BATCH*NANCH];
__device__ float g_pad_hi[(size_t)BATCH*CIN*PFLAT];
__device__ float g_pad_lo[(size_t)BATCH*CIN*PFLAT];

// ---- helpers ----
__device__ __forceinline__ float tf32r(float x) {
    unsigned int u;
    asm("cvt.rna.tf32.f32 %0, %1;" : "=r"(u) : "f"(x));
    return __uint_as_float(u);
}
__device__ __forceinline__ void mma8(float (&d)[4], const uint32_t (&a)[4], const uint32_t (&b)[2]) {
    asm volatile(
        "mma.sync.aligned.m16n8k8.row.col.f32.tf32.tf32.f32 "
        "{%0,%1,%2,%3}, {%4,%5,%6,%7}, {%8,%9}, {%0,%1,%2,%3};"
        : "+f"(d[0]), "+f"(d[1]), "+f"(d[2]), "+f"(d[3])
        : "r"(a[0]), "r"(a[1]), "r"(a[2]), "r"(a[3]), "r"(b[0]), "r"(b[1]));
}
__device__ __forceinline__ void cpa4(unsigned int dst, const void* src) {
    asm volatile("cp.async.ca.shared.global [%0], [%1], 4;" :: "r"(dst), "l"(src));
}
__device__ __forceinline__ void cp_commit() { asm volatile("cp.async.commit_group;"); }
__device__ __forceinline__ void cp_wait0()  { asm volatile("cp.async.wait_group 0;"); }

// ============================================================
// Kernel 0: padded input + tf32 hi/lo split (for tensor path)
// ============================================================
__global__ void prep_pad_kernel(const float* __restrict__ x)
{
    int idx = blockIdx.x * blockDim.x + threadIdx.x;
    const int total = BATCH * CIN * PFLAT;
    if (idx >= total) return;
    int f = idx % PFLAT;
    int bc = idx / PFLAT;
    int yy = f / PADW, xx = f % PADW;
    float v = 0.f;
    if (yy >= 1 && yy <= HH && xx >= 1 && xx <= WW)
        v = x[(size_t)bc * NPX + (yy - 1) * WW + (xx - 1)];
    float hi = tf32r(v);
    g_pad_hi[idx] = hi;
    g_pad_lo[idx] = tf32r(v - hi);
}

// ============================================================
// Hybrid conv kernel: role by blockIdx.x
//   MMA role: 128px x 64k, 16-ch chunks, split-TF32 mma.sync
//   FFMA role: R11 scalar kernel verbatim (bitwise-anchored)
// uniform smem 69632B -> 2 blocks/SM (reg-limited via launch_bounds)
// ============================================================
#define WSTR 248
#define WRSTR 148
#define MMA_SMEM_FLOATS (32*WSTR + 64*WRSTR)   // 7936 + 9472 = 17408
#define F_IN_TILE (8*4*68)
#define F_W_TILE  (8*9*68)
#define HYB_SMEM (MMA_SMEM_FLOATS*4)           // 69632 >= ffma 56576

__device__ void mma_role(float* s, const float* __restrict__ w, const float* __restrict__ bias,
                         int o0, int k0, int b)
{
    float* winh = s;                 // [16][248]
    float* winl = s + 16 * WSTR;
    float* wraw = s + 32 * WSTR;     // [64][148]

    const int tid = threadIdx.x;
    const int wid = tid >> 5;
    const int lane = tid & 31;
    const int l4 = lane & 3;
    const int lg = lane >> 2;
    const int wm = wid & 3;
    const int wn = wid >> 2;

    const float* wk = w + (size_t)k0 * (CIN * 9);
    const size_t pbase = (size_t)b * CIN * PFLAT;

    float tot[2][4][4];
#pragma unroll
    for (int i = 0; i < 2; ++i)
#pragma unroll
        for (int j = 0; j < 4; ++j)
#pragma unroll
            for (int r = 0; r < 4; ++r) tot[i][j][r] = 0.f;

    for (int chunk = 0; chunk < 32; ++chunk) {
        const int c0 = chunk * 16;

        for (int idx = tid; idx < 16 * 234; idx += 256) {
            int c = idx / 234, j = idx - c * 234;
            size_t g = pbase + (size_t)(c0 + c) * PFLAT + o0 + j;
            winh[c * WSTR + j] = g_pad_hi[g];
            winl[c * WSTR + j] = g_pad_lo[g];
        }
        for (int idx = tid; idx < 64 * 144; idx += 256) {
            int k = idx / 144, r = idx - k * 144;
            wraw[k * WRSTR + r] = wk[(size_t)k * (CIN * 9) + c0 * 9 + r];
        }
        __syncthreads();

        float dch[2][4][4];
#pragma unroll
        for (int i = 0; i < 2; ++i)
#pragma unroll
            for (int j = 0; j < 4; ++j)
#pragma unroll
                for (int r = 0; r < 4; ++r) dch[i][j][r] = 0.f;

        for (int q = 0; q < 9; ++q) {
            const int sq = (q / 3) * PADW + (q - (q / 3) * 3);
#pragma unroll
            for (int cs = 0; cs < 2; ++cs) {
                const int cc = cs * 8;

                uint32_t bhi[4][2], blo[4][2];
#pragma unroll
                for (int j = 0; j < 4; ++j) {
                    int n = wn * 32 + j * 8 + lg;
                    float r0 = wraw[n * WRSTR + (cc + l4) * 9 + q];
                    float r1 = wraw[n * WRSTR + (cc + l4 + 4) * 9 + q];
                    float h0 = tf32r(r0), h1 = tf32r(r1);
                    bhi[j][0] = __float_as_uint(h0);
                    bhi[j][1] = __float_as_uint(h1);
                    blo[j][0] = __float_as_uint(tf32r(r0 - h0));
                    blo[j][1] = __float_as_uint(tf32r(r1 - h1));
                }
                uint32_t ahi[2][4], alo[2][4];
#pragma unroll
                for (int i = 0; i < 2; ++i) {
                    int m0 = wm * 32 + i * 16 + lg;
                    int b0 = (cc + l4) * WSTR + m0 + sq;
                    int b1 = (cc + l4 + 4) * WSTR + m0 + sq;
                    ahi[i][0] = __float_as_uint(winh[b0]);
                    ahi[i][1] = __float_as_uint(winh[b0 + 8]);
                    ahi[i][2] = __float_as_uint(winh[b1]);
                    ahi[i][3] = __float_as_uint(winh[b1 + 8]);
                    alo[i][0] = __float_as_uint(winl[b0]);
                    alo[i][1] = __float_as_uint(winl[b0 + 8]);
                    alo[i][2] = __float_as_uint(winl[b1]);
                    alo[i][3] = __float_as_uint(winl[b1 + 8]);
                }
#pragma unroll
                for (int i = 0; i < 2; ++i)
#pragma unroll
                    for (int j = 0; j < 4; ++j) mma8(dch[i][j], ahi[i], bhi[j]);
#pragma unroll
                for (int i = 0; i < 2; ++i)
#pragma unroll
                    for (int j = 0; j < 4; ++j) mma8(dch[i][j], alo[i], bhi[j]);
#pragma unroll
                for (int i = 0; i < 2; ++i)
#pragma unroll
                    for (int j = 0; j < 4; ++j) mma8(dch[i][j], ahi[i], blo[j]);
            }
        }
        __syncthreads();

#pragma unroll
        for (int i = 0; i < 2; ++i)
#pragma unroll
            for (int j = 0; j < 4; ++j)
#pragma unroll
                for (int r = 0; r < 4; ++r) tot[i][j][r] += dch[i][j][r];
    }

    const size_t bbase = (size_t)b * CIN * NPX;
#pragma unroll
    for (int i = 0; i < 2; ++i) {
#pragma unroll
        for (int j = 0; j < 4; ++j) {
            int nb = k0 + wn * 32 + j * 8 + l4 * 2;
            float bv0 = bias[nb], bv1 = bias[nb + 1];
            int o = o0 + wm * 32 + i * 16 + lg;
            {
                int y = o / PADW, xcol = o - y * PADW;
                if (y < HH && xcol < WW) {
                    int px = y * WW + xcol;
                    g_feat[bbase + (size_t)nb * NPX + px]       = fmaxf(tot[i][j][0] + bv0, 0.f);
                    g_feat[bbase + (size_t)(nb + 1) * NPX + px] = fmaxf(tot[i][j][1] + bv1, 0.f);
                }
            }
            {
                int o2 = o + 8;
                int y = o2 / PADW, xcol = o2 - y * PADW;
                if (y < HH && xcol < WW) {
                    int px = y * WW + xcol;
                    g_feat[bbase + (size_t)nb * NPX + px]       = fmaxf(tot[i][j][2] + bv0, 0.f);
                    g_feat[bbase + (size_t)(nb + 1) * NPX + px] = fmaxf(tot[i][j][3] + bv1, 0.f);
                }
            }
        }
    }
}

__device__ void ffma_role(float* cs_, const float* __restrict__ x, const float* __restrict__ w,
                          const float* __restrict__ bias, int r0, int k0, int b)
{
    float* sIn = cs_;
    float* sW  = cs_ + 2 * F_IN_TILE;
    const unsigned int sbase = (unsigned int)__cvta_generic_to_shared(cs_);

    const int tid = threadIdx.x;
    const int kg = tid >> 4;
    const int pxg = tid & 15;

    const float* xb = x + (size_t)b * CIN * NPX;
    const float* wk = w + (size_t)k0 * (CIN * 9);

    int inoff[9];
#pragma unroll
    for (int t = 0; t < 9; ++t) {
        int idx = tid + 256 * t;
        if (idx < F_IN_TILE) {
            int c = idx / 272; int rem = idx % 272;
            int r = rem / 68;  int xx = rem % 68;
            int gy = r0 - 1 + r;
            int gx = xx - 1;
            bool ok = (xx < 66) && ((unsigned)gy < (unsigned)HH) && ((unsigned)gx < (unsigned)WW);
            inoff[t] = ok ? (c * NPX + gy * WW + gx) : -1;
        } else inoff[t] = -2;
    }
#pragma unroll
    for (int t = 0; t < 9; ++t) {
        if (inoff[t] == -1) {
            sIn[0 * F_IN_TILE + tid + 256 * t] = 0.f;
            sIn[1 * F_IN_TILE + tid + 256 * t] = 0.f;
        }
    }

    auto load_chunk = [&](int ch, int buf) {
        const int ginc = ch * 8 * NPX;
        const int winc = ch * 72;
        const unsigned int dInB = sbase + (unsigned int)(buf * F_IN_TILE) * 4u;
        const unsigned int dWB  = sbase + (unsigned int)(2 * F_IN_TILE + buf * F_W_TILE) * 4u;
#pragma unroll
        for (int t = 0; t < 9; ++t) {
            int o = inoff[t];
            if (o >= 0)
                cpa4(dInB + (unsigned int)(tid + 256 * t) * 4u, xb + ginc + o);
        }
#pragma unroll
        for (int t = 0; t < 5; ++t) {
            int v4 = tid + 256 * t;
            if (v4 < 1152) {
                int kk = v4 / 18;
                int f  = v4 - kk * 18;
                const float* src = &wk[(size_t)kk * (CIN * 9) + winc + f * 4];
#pragma unroll
                for (int j = 0; j < 4; ++j) {
                    int e = f * 4 + j;
                    int c = e / 9;
                    int q = e - c * 9;
                    cpa4(dWB + (unsigned int)(c * 612 + q * 68 + kk) * 4u, src + j);
                }
            }
        }
    };

    float tot[4][8];
#pragma unroll
    for (int jj = 0; jj < 4; ++jj)
#pragma unroll
        for (int i = 0; i < 8; ++i) tot[jj][i] = 0.f;

    load_chunk(0, 0);
    cp_commit();
    cp_wait0();
    __syncthreads();

    for (int ch = 0; ch < CIN / 8; ++ch) {
        const int cur = ch & 1;
        const bool more = (ch + 1 < CIN / 8);
        if (more) { load_chunk(ch + 1, cur ^ 1); cp_commit(); }

        const float* bIn = sIn + cur * F_IN_TILE;
        const float* bW  = sW  + cur * F_W_TILE + kg * 4;

        float acc[4][8];
#pragma unroll
        for (int jj = 0; jj < 4; ++jj)
#pragma unroll
            for (int i = 0; i < 8; ++i) acc[jj][i] = 0.f;

#pragma unroll
        for (int c = 0; c < 8; ++c) {
            float rows[4][6];
#pragma unroll
            for (int r = 0; r < 4; ++r) {
                const float4 v4 = *(const float4*)&bIn[c * 272 + r * 68 + 4 * pxg];
                const float2 v2 = *(const float2*)&bIn[c * 272 + r * 68 + 4 * pxg + 4];
                rows[r][0] = v4.x; rows[r][1] = v4.y; rows[r][2] = v4.z; rows[r][3] = v4.w;
                rows[r][4] = v2.x; rows[r][5] = v2.y;
            }
#pragma unroll
            for (int dy = 0; dy < 3; ++dy) {
#pragma unroll
                for (int dx = 0; dx < 3; ++dx) {
                    const float4 wq = *(const float4*)&bW[c * 612 + (dy * 3 + dx) * 68];
                    const float wv[4] = {wq.x, wq.y, wq.z, wq.w};
#pragma unroll
                    for (int jj = 0; jj < 4; ++jj)
#pragma unroll
                        for (int ro = 0; ro < 2; ++ro)
#pragma unroll
                            for (int u = 0; u < 4; ++u)
                                acc[jj][ro * 4 + u] =
                                    fmaf(wv[jj], rows[ro + dy][u + dx], acc[jj][ro * 4 + u]);
                }
            }
        }
#pragma unroll
        for (int jj = 0; jj < 4; ++jj)
#pragma unroll
            for (int i = 0; i < 8; ++i) tot[jj][i] += acc[jj][i];

        if (more) cp_wait0();
        __syncthreads();
    }

#pragma unroll
    for (int ro = 0; ro < 2; ++ro) {
        int row = r0 + ro;
#pragma unroll
        for (int u = 0; u < 4; ++u) {
            int col = 4 * pxg + u;
            if (col < WW) {
#pragma unroll
                for (int jj = 0; jj < 4; ++jj) {
                    int k = k0 + kg * 4 + jj;
                    float v = tot[jj][ro * 4 + u] + bias[k];
                    v = fmaxf(v, 0.f);
                    g_feat[((size_t)b * CIN + k) * NPX + row * WW + col] = v;
                }
            }
        }
    }
}

__global__ __launch_bounds__(256, 2) void conv_hybrid_kernel(
    const float* __restrict__ x, const float* __restrict__ w, const float* __restrict__ bias)
{
    extern __shared__ float s[];
    const int bx = blockIdx.x;
    const int b  = blockIdx.y;
    if (bx < MMA_BLKS) {
        int o0 = (bx % 21) * 128;
        int k0 = (bx / 21) * 64;
        mma_role(s, w, bias, o0, k0, b);
    } else {
        int r = bx - MMA_BLKS;
        int r0 = (r % 25) * 2;
        int k0 = KSPLIT + (r / 25) * 64;
        ffma_role(s, x, w, bias, r0, k0, b);
    }
}

// ============================================================
// Kernel 2: fused 1x1 heads + anchor decode. (unchanged)
// ============================================================
__global__ __launch_bounds__(256) void heads_decode_kernel(
    const float* __restrict__ wc, const float* __restrict__ bc,
    const float* __restrict__ wr, const float* __restrict__ brg)
{
    extern __shared__ float X[];
    __shared__ float scls[32 * 18];
    __shared__ float sreg[32 * 36];

    const int b = blockIdx.y;
    const int p0 = blockIdx.x * 32;
    const int tid = threadIdx.x;

    for (int idx = tid; idx < CIN * 32; idx += 256) {
        int c = idx >> 5; int j = idx & 31;
        int p = p0 + j;
        X[idx] = (p < NPX) ? g_feat[((size_t)b * CIN + c) * NPX + p] : 0.f;
    }
    __syncthreads();

    for (int t = tid; t < 54 * 8; t += 256) {
        int o = t >> 3;
        int j0 = (t & 7) * 4;
        float bb = (o < 18) ? bc[o] : brg[o - 18];
        const float* W = (o < 18) ? (wc + (size_t)o * CIN) : (wr + (size_t)(o - 18) * CIN);
        float t0 = 0.f, t1 = 0.f, t2 = 0.f, t3 = 0.f;
        for (int cc = 0; cc < CIN; cc += 8) {
            float a0 = 0.f, a1 = 0.f, a2 = 0.f, a3 = 0.f;
#pragma unroll
            for (int u = 0; u < 8; ++u) {
                int c = cc + u;
                float wv = __ldg(&W[c]);
                const float4 xv = *(const float4*)&X[c * 32 + j0];
                a0 = fmaf(wv, xv.x, a0);
                a1 = fmaf(wv, xv.y, a1);
                a2 = fmaf(wv, xv.z, a2);
                a3 = fmaf(wv, xv.w, a3);
            }
            t0 += a0; t1 += a1; t2 += a2; t3 += a3;
        }
        float accs[4] = {t0 + bb, t1 + bb, t2 + bb, t3 + bb};
#pragma unroll
        for (int jj = 0; jj < 4; ++jj) {
            int j = j0 + jj;
            if (o < 18) scls[j * 18 + o] = accs[jj];
            else        sreg[j * 36 + (o - 18)] = accs[jj];
        }
    }
    __syncthreads();

    for (int t = tid; t < 32 * NA; t += 256) {
        int j = t / NA;
        int a = t % NA;
        int p = p0 + j;
        if (p >= NPX) continue;
        int yy = p / WW;
        int xx = p % WW;

        int ri = a / 3, si = a % 3;
        float ratio = (ri == 0) ? 0.5f : (ri == 1 ? 1.0f : 2.0f);
        float scale = (si == 0) ? 8.0f : (si == 1 ? 16.0f : 32.0f);
        float ah = 16.0f * scale * sqrtf(ratio);
        float aw = 16.0f * scale * sqrtf(1.0f / ratio);
        float sy = yy * 16.0f, sx = xx * 16.0f;
        float ay1 = sy + 8.0f - ah * 0.5f;
        float ax1 = sx + 8.0f - aw * 0.5f;
        float ay2 = sy + 8.0f + ah * 0.5f;
        float ax2 = sx + 8.0f + aw * 0.5f;

        float h = ay2 - ay1;
        float w = ax2 - ax1;
        float cy = ay1 + 0.5f * h;
        float cx = ax1 + 0.5f * w;

        const float* rg = &sreg[j * 36 + a * 4];
        float ncy = rg[0] * h + cy;
        float ncx = rg[1] * w + cx;
        float nh = h * expf(rg[2]);
        float nw = w * expf(rg[3]);

        float y1 = fminf(fmaxf(ncy - 0.5f * nh, 0.f), IMGF);
        float x1 = fminf(fmaxf(ncx - 0.5f * nw, 0.f), IMGF);
        float y2 = fminf(fmaxf(ncy + 0.5f * nh, 0.f), IMGF);
        float x2 = fminf(fmaxf(ncx + 0.5f * nw, 0.f), IMGF);

        float hs = y2 - y1, ws = x2 - x1;
        bool valid = (hs >= MIN_SIZE) && (ws >= MIN_SIZE);

        float c0 = scls[j * 18 + a * 2 + 0], c1 = scls[j * 18 + a * 2 + 1];
        float m = fmaxf(c0, c1);
        float e0 = expf(c0 - m);
        float e1 = expf(c1 - m);
        float score = e1 / (e0 + e1);

        int n = p * NA + a;
        float* bx = &g_boxes[((size_t)b * NANCH + n) * 4];
        bx[0] = y1; bx[1] = x1; bx[2] = y2; bx[3] = x2;
        g_key[(size_t)b * NANCH + n] = valid ? (__float_as_uint(score) | 0x80000000u) : 0u;
    }
}

// ============================================================
// Kernel 3: propose (unchanged)
// ============================================================
#define PROP_SMEM 160256

__global__ __launch_bounds__(1024) void propose_kernel(float* __restrict__ out)
{
    extern __shared__ unsigned char smem[];
    unsigned int* skey = (unsigned int*)smem;
    unsigned long long* cand = (unsigned long long*)(smem + 90112);
    float* sb     = (float*)smem;
    float* sarea  = (float*)(smem + 16000);
    float* sscore = (float*)(smem + 20000);
    unsigned int* mask = (unsigned int*)(smem + 24000);
    int* sA = (int*)(smem + 152064);
    int* sB = (int*)(smem + 152064 + 4096);
    __shared__ int s_cnt;
    __shared__ unsigned int s_T;
    __shared__ int s_nc;
    __shared__ int s_NK;
    __shared__ unsigned int kw[32];

    const int b = blockIdx.x;
    const int tid = threadIdx.x;
    const int wid = tid >> 5;
    const int lane = tid & 31;
    const unsigned int* gk = g_key + (size_t)b * NANCH;

    for (int n = tid; n < NANCH; n += 1024) skey[n] = gk[n];
    if (tid == 0) s_T = 0u;
    __syncthreads();

    for (int bit = 31; bit >= 0; --bit) {
        unsigned int T2 = s_T | (1u << bit);
        if (tid == 0) s_cnt = 0;
        __syncthreads();
        int c = 0;
        for (int n = tid; n < NANCH; n += 1024) c += (skey[n] >= T2) ? 1 : 0;
#pragma unroll
        for (int o = 16; o; o >>= 1) c += __shfl_down_sync(0xFFFFFFFFu, c, o);
        if (lane == 0) atomicAdd(&s_cnt, c);
        __syncthreads();
        if (tid == 0 && s_cnt >= PRE_NMS) s_T = T2;
        __syncthreads();
    }
    unsigned int T = s_T;
    if (tid == 0) s_nc = 0;
    __syncthreads();

    for (int n = tid; n < NANCH; n += 1024) {
        unsigned int k = skey[n];
        if (k >= T) {
            int pos = atomicAdd(&s_nc, 1);
            if (pos < 2048)
                cand[pos] = ((unsigned long long)k << 32) | (unsigned int)(~n);
        }
    }
    __syncthreads();
    int nc = min(s_nc, 2048);
    for (int i = tid; i < 2048; i += 1024)
        if (i >= nc) cand[i] = 0ull;
    __syncthreads();

    for (int k = 2; k <= 2048; k <<= 1) {
        for (int j = k >> 1; j > 0; j >>= 1) {
            __syncthreads();
#pragma unroll
            for (int base = 0; base < 2048; base += 1024) {
                int i = base + tid;
                int ixj = i ^ j;
                if (ixj > i) {
                    unsigned long long a = cand[i], c2 = cand[ixj];
                    bool up = ((i & k) == 0);
                    bool swap = up ? (a < c2) : (a > c2);
                    if (swap) { cand[i] = c2; cand[ixj] = a; }
                }
            }
        }
    }
    __syncthreads();

    float myScore = 0.f;
    if (tid < PRE_NMS) {
        unsigned long long ck = cand[tid];
        unsigned int idx = ~(unsigned int)(ck & 0xFFFFFFFFull);
        if (idx >= (unsigned)NANCH) idx = 0;
        const float* bx = g_boxes + ((size_t)b * NANCH + idx) * 4;
        float y1 = bx[0], x1 = bx[1], y2 = bx[2], x2 = bx[3];
        sb[tid * 4 + 0] = y1; sb[tid * 4 + 1] = x1;
        sb[tid * 4 + 2] = y2; sb[tid * 4 + 3] = x2;
        sarea[tid] = (y2 - y1) * (x2 - x1);
        unsigned int kb = (unsigned int)(ck >> 32);
        myScore = __uint_as_float(kb ^ 0x80000000u);
        sscore[tid] = myScore;
    }
    __syncthreads();

    for (int i = wid; i < PRE_NMS; i += 32) {
        const float4 bi = ((const float4*)sb)[i];
        const float ai = sarea[i];
#pragma unroll 4
        for (int w0 = 0; w0 < 32; ++w0) {
            int j = w0 * 32 + lane;
            bool sup = false;
            if (j > i && j < PRE_NMS) {
                const float4 bj = ((const float4*)sb)[j];
                float ty = fmaxf(bi.x, bj.x);
                float tx = fmaxf(bi.y, bj.y);
                float by = fminf(bi.z, bj.z);
                float bxx = fminf(bi.w, bj.w);
                float ih = fmaxf(by - ty, 0.f);
                float iw = fmaxf(bxx - tx, 0.f);
                float inter = ih * iw;
                float iou = inter / (ai + sarea[j] - inter + 1e-9f);
                sup = iou > NMS_THR;
            }
            unsigned int word = __ballot_sync(0xFFFFFFFFu, sup);
            if (lane == 0) mask[i * 32 + w0] = word;
        }
    }
    if (tid < 32) kw[tid] = 0xFFFFFFFFu;
    __syncthreads();

    if (tid < 32) {
        for (int i = 0; i < PRE_NMS; ++i) {
            unsigned int w = kw[i >> 5];
            if ((w >> (i & 31)) & 1u)
                kw[tid] &= ~mask[i * 32 + tid];
            __syncwarp();
        }
    }
    __syncthreads();

    int keepv = (tid < PRE_NMS) ? (int)((kw[tid >> 5] >> (tid & 31)) & 1u) : 0;
    sA[tid] = keepv;
    __syncthreads();
    int* src = sA; int* dst = sB;
    for (int d = 1; d < 1024; d <<= 1) {
        int v = src[tid];
        if (tid >= d) v += src[tid - d];
        dst[tid] = v;
        __syncthreads();
        int* t = src; src = dst; dst = t;
    }
    if (tid == 0) s_NK = src[PRE_NMS - 1];
    __syncthreads();
    int NK = s_NK;

    float* ob = out + (size_t)b * POST_NMS * 5;
    if (tid < PRE_NMS) {
        int incl = src[tid];
        int excl = incl - keepv;
        int slot; float sc;
        if (keepv) { slot = excl; sc = myScore; }
        else       { slot = NK + (tid - excl); sc = -1e30f; }
        if (slot < POST_NMS) {
            ob[slot * 5 + 0] = sb[tid * 4 + 0];
            ob[slot * 5 + 1] = sb[tid * 4 + 1];
            ob[slot * 5 + 2] = sb[tid * 4 + 2];
            ob[slot * 5 + 3] = sb[tid * 4 + 3];
            ob[slot * 5 + 4] = sc;
        }
    }
}

// ============================================================
extern "C" void kernel_launch(void* const* d_in, const int* in_sizes, int n_in,
                              void* d_out, int out_size)
{
    const float* x       = (const float*)d_in[0];
    const float* w_share = (const float*)d_in[1];
    const float* b_share = (const float*)d_in[2];
    const float* w_cls   = (const float*)d_in[3];
    const float* b_cls   = (const float*)d_in[4];
    const float* w_reg   = (const float*)d_in[5];
    const float* b_reg   = (const float*)d_in[6];
    float* out = (float*)d_out;

    cudaFuncSetAttribute(conv_hybrid_kernel, cudaFuncAttributeMaxDynamicSharedMemorySize, HYB_SMEM);
    cudaFuncSetAttribute(heads_decode_kernel, cudaFuncAttributeMaxDynamicSharedMemorySize, CIN * 32 * 4);
    cudaFuncSetAttribute(propose_kernel, cudaFuncAttributeMaxDynamicSharedMemorySize, PROP_SMEM);

    const int prep_total = BATCH * CIN * PFLAT;
    prep_pad_kernel<<<(prep_total + 255) / 256, 256>>>(x);
    conv_hybrid_kernel<<<dim3(MMA_BLKS + FMA_BLKS, BATCH), 256, HYB_SMEM>>>(x, w_share, b_share);
    heads_decode_kernel<<<dim3((NPX + 31) / 32, BATCH), 256, CIN * 32 * 4>>>(w_cls, b_cls, w_reg, b_reg);
    propose_kernel<<<BATCH, 1024, PROP_SMEM>>>(out);
}

// round 17
// speedup vs baseline: 1.2475x; 1.0415x over previous
#include <cuda_runtime.h>
#include <cuda_bf16.h>
#include <cstdint>

// ---------------- problem constants ----------------
#define BATCH 8
#define CIN 512
#define HH 50
#define WW 50
#define NPX (HH*WW)          // 2500
#define NA 9
#define NANCH (NPX*NA)       // 22500
#define PRE_NMS 1000
#define POST_NMS 300
#define NMS_THR 0.7f
#define IMGF 800.0f
#define MIN_SIZE 16.0f

#define PADW 52
#define PADH 56
#define PFLAT (PADW*PADH)    // 2912

#define KSPLIT 256
#define MMA_JOBS_TOTAL (84*BATCH)    // 672
#define FMA_JOBS_TOTAL (100*BATCH)   // 800
#define CONV_BLOCKS 1472             // 672 + 800
#define FFMA_ELSE_COVER 732          // else-branch covers fidx [0,732); overflow continues here

// ---------------- device scratch (static; no allocations allowed) ----------------
__device__ float g_feat[(size_t)BATCH*CIN*NPX];
__device__ float g_boxes[(size_t)BATCH*NANCH*4];
__device__ unsigned int g_key[(size_t)BATCH*NANCH];
__device__ float g_pad_hi[(size_t)BATCH*CIN*PFLAT];
__device__ float g_pad_lo[(size_t)BATCH*CIN*PFLAT];

// ---- helpers ----
__device__ __forceinline__ float tf32r(float x) {
    unsigned int u;
    asm("cvt.rna.tf32.f32 %0, %1;" : "=r"(u) : "f"(x));
    return __uint_as_float(u);
}
__device__ __forceinline__ void mma8(float (&d)[4], const uint32_t (&a)[4], const uint32_t (&b)[2]) {
    asm volatile(
        "mma.sync.aligned.m16n8k8.row.col.f32.tf32.tf32.f32 "
        "{%0,%1,%2,%3}, {%4,%5,%6,%7}, {%8,%9}, {%0,%1,%2,%3};"
        : "+f"(d[0]), "+f"(d[1]), "+f"(d[2]), "+f"(d[3])
        : "r"(a[0]), "r"(a[1]), "r"(a[2]), "r"(a[3]), "r"(b[0]), "r"(b[1]));
}
__device__ __forceinline__ void cpa4(unsigned int dst, const void* src) {
    asm volatile("cp.async.ca.shared.global [%0], [%1], 4;" :: "r"(dst), "l"(src));
}
__device__ __forceinline__ void cp_commit() { asm volatile("cp.async.commit_group;"); }
__device__ __forceinline__ void cp_wait0()  { asm volatile("cp.async.wait_group 0;"); }

// ============================================================
// Kernel 0: padded input + tf32 hi/lo split (for tensor path)
// ============================================================
__global__ void prep_pad_kernel(const float* __restrict__ x)
{
    int idx = blockIdx.x * blockDim.x + threadIdx.x;
    const int total = BATCH * CIN * PFLAT;
    if (idx >= total) return;
    int f = idx % PFLAT;
    int bc = idx / PFLAT;
    int yy = f / PADW, xx = f % PADW;
    float v = 0.f;
    if (yy >= 1 && yy <= HH && xx >= 1 && xx <= WW)
        v = x[(size_t)bc * NPX + (yy - 1) * WW + (xx - 1)];
    float hi = tf32r(v);
    g_pad_hi[idx] = hi;
    g_pad_lo[idx] = tf32r(v - hi);
}

// ============================================================
// Hybrid conv kernel (role functions VERBATIM from R15 passing kernel;
// block->role map anti-correlates roles on co-resident SM slots:
// groups of 296, positions [0,148)=MMA-side, [148,296)=FFMA-side).
// ============================================================
#define WSTR 248
#define WRSTR 148
#define MMA_SMEM_FLOATS (32*WSTR + 64*WRSTR)   // 17408
#define F_IN_TILE (8*4*68)
#define F_W_TILE  (8*9*68)
#define HYB_SMEM (MMA_SMEM_FLOATS*4)           // 69632

__device__ void mma_role(float* s, const float* __restrict__ w, const float* __restrict__ bias,
                         int o0, int k0, int b)
{
    float* winh = s;
    float* winl = s + 16 * WSTR;
    float* wraw = s + 32 * WSTR;

    const int tid = threadIdx.x;
    const int wid = tid >> 5;
    const int lane = tid & 31;
    const int l4 = lane & 3;
    const int lg = lane >> 2;
    const int wm = wid & 3;
    const int wn = wid >> 2;

    const float* wk = w + (size_t)k0 * (CIN * 9);
    const size_t pbase = (size_t)b * CIN * PFLAT;

    float tot[2][4][4];
#pragma unroll
    for (int i = 0; i < 2; ++i)
#pragma unroll
        for (int j = 0; j < 4; ++j)
#pragma unroll
            for (int r = 0; r < 4; ++r) tot[i][j][r] = 0.f;

    for (int chunk = 0; chunk < 32; ++chunk) {
        const int c0 = chunk * 16;

        for (int idx = tid; idx < 16 * 234; idx += 256) {
            int c = idx / 234, j = idx - c * 234;
            size_t g = pbase + (size_t)(c0 + c) * PFLAT + o0 + j;
            winh[c * WSTR + j] = g_pad_hi[g];
            winl[c * WSTR + j] = g_pad_lo[g];
        }
        for (int idx = tid; idx < 64 * 144; idx += 256) {
            int k = idx / 144, r = idx - k * 144;
            wraw[k * WRSTR + r] = wk[(size_t)k * (CIN * 9) + c0 * 9 + r];
        }
        __syncthreads();

        float dch[2][4][4];
#pragma unroll
        for (int i = 0; i < 2; ++i)
#pragma unroll
            for (int j = 0; j < 4; ++j)
#pragma unroll
                for (int r = 0; r < 4; ++r) dch[i][j][r] = 0.f;

        for (int q = 0; q < 9; ++q) {
            const int sq = (q / 3) * PADW + (q - (q / 3) * 3);
#pragma unroll
            for (int cs = 0; cs < 2; ++cs) {
                const int cc = cs * 8;

                uint32_t bhi[4][2], blo[4][2];
#pragma unroll
                for (int j = 0; j < 4; ++j) {
                    int n = wn * 32 + j * 8 + lg;
                    float r0 = wraw[n * WRSTR + (cc + l4) * 9 + q];
                    float r1 = wraw[n * WRSTR + (cc + l4 + 4) * 9 + q];
                    float h0 = tf32r(r0), h1 = tf32r(r1);
                    bhi[j][0] = __float_as_uint(h0);
                    bhi[j][1] = __float_as_uint(h1);
                    blo[j][0] = __float_as_uint(tf32r(r0 - h0));
                    blo[j][1] = __float_as_uint(tf32r(r1 - h1));
                }
                uint32_t ahi[2][4], alo[2][4];
#pragma unroll
                for (int i = 0; i < 2; ++i) {
                    int m0 = wm * 32 + i * 16 + lg;
                    int b0 = (cc + l4) * WSTR + m0 + sq;
                    int b1 = (cc + l4 + 4) * WSTR + m0 + sq;
                    ahi[i][0] = __float_as_uint(winh[b0]);
                    ahi[i][1] = __float_as_uint(winh[b0 + 8]);
                    ahi[i][2] = __float_as_uint(winh[b1]);
                    ahi[i][3] = __float_as_uint(winh[b1 + 8]);
                    alo[i][0] = __float_as_uint(winl[b0]);
                    alo[i][1] = __float_as_uint(winl[b0 + 8]);
                    alo[i][2] = __float_as_uint(winl[b1]);
                    alo[i][3] = __float_as_uint(winl[b1 + 8]);
                }
#pragma unroll
                for (int i = 0; i < 2; ++i)
#pragma unroll
                    for (int j = 0; j < 4; ++j) mma8(dch[i][j], ahi[i], bhi[j]);
#pragma unroll
                for (int i = 0; i < 2; ++i)
#pragma unroll
                    for (int j = 0; j < 4; ++j) mma8(dch[i][j], alo[i], bhi[j]);
#pragma unroll
                for (int i = 0; i < 2; ++i)
#pragma unroll
                    for (int j = 0; j < 4; ++j) mma8(dch[i][j], ahi[i], blo[j]);
            }
        }
        __syncthreads();

#pragma unroll
        for (int i = 0; i < 2; ++i)
#pragma unroll
            for (int j = 0; j < 4; ++j)
#pragma unroll
                for (int r = 0; r < 4; ++r) tot[i][j][r] += dch[i][j][r];
    }

    const size_t bbase = (size_t)b * CIN * NPX;
#pragma unroll
    for (int i = 0; i < 2; ++i) {
#pragma unroll
        for (int j = 0; j < 4; ++j) {
            int nb = k0 + wn * 32 + j * 8 + l4 * 2;
            float bv0 = bias[nb], bv1 = bias[nb + 1];
            int o = o0 + wm * 32 + i * 16 + lg;
            {
                int y = o / PADW, xcol = o - y * PADW;
                if (y < HH && xcol < WW) {
                    int px = y * WW + xcol;
                    g_feat[bbase + (size_t)nb * NPX + px]       = fmaxf(tot[i][j][0] + bv0, 0.f);
                    g_feat[bbase + (size_t)(nb + 1) * NPX + px] = fmaxf(tot[i][j][1] + bv1, 0.f);
                }
            }
            {
                int o2 = o + 8;
                int y = o2 / PADW, xcol = o2 - y * PADW;
                if (y < HH && xcol < WW) {
                    int px = y * WW + xcol;
                    g_feat[bbase + (size_t)nb * NPX + px]       = fmaxf(tot[i][j][2] + bv0, 0.f);
                    g_feat[bbase + (size_t)(nb + 1) * NPX + px] = fmaxf(tot[i][j][3] + bv1, 0.f);
                }
            }
        }
    }
}

__device__ void ffma_role(float* cs_, const float* __restrict__ x, const float* __restrict__ w,
                          const float* __restrict__ bias, int r0, int k0, int b)
{
    float* sIn = cs_;
    float* sW  = cs_ + 2 * F_IN_TILE;
    const unsigned int sbase = (unsigned int)__cvta_generic_to_shared(cs_);

    const int tid = threadIdx.x;
    const int kg = tid >> 4;
    const int pxg = tid & 15;

    const float* xb = x + (size_t)b * CIN * NPX;
    const float* wk = w + (size_t)k0 * (CIN * 9);

    int inoff[9];
#pragma unroll
    for (int t = 0; t < 9; ++t) {
        int idx = tid + 256 * t;
        if (idx < F_IN_TILE) {
            int c = idx / 272; int rem = idx % 272;
            int r = rem / 68;  int xx = rem % 68;
            int gy = r0 - 1 + r;
            int gx = xx - 1;
            bool ok = (xx < 66) && ((unsigned)gy < (unsigned)HH) && ((unsigned)gx < (unsigned)WW);
            inoff[t] = ok ? (c * NPX + gy * WW + gx) : -1;
        } else inoff[t] = -2;
    }
#pragma unroll
    for (int t = 0; t < 9; ++t) {
        if (inoff[t] == -1) {
            sIn[0 * F_IN_TILE + tid + 256 * t] = 0.f;
            sIn[1 * F_IN_TILE + tid + 256 * t] = 0.f;
        }
    }

    auto load_chunk = [&](int ch, int buf) {
        const int ginc = ch * 8 * NPX;
        const int winc = ch * 72;
        const unsigned int dInB = sbase + (unsigned int)(buf * F_IN_TILE) * 4u;
        const unsigned int dWB  = sbase + (unsigned int)(2 * F_IN_TILE + buf * F_W_TILE) * 4u;
#pragma unroll
        for (int t = 0; t < 9; ++t) {
            int o = inoff[t];
            if (o >= 0)
                cpa4(dInB + (unsigned int)(tid + 256 * t) * 4u, xb + ginc + o);
        }
#pragma unroll
        for (int t = 0; t < 5; ++t) {
            int v4 = tid + 256 * t;
            if (v4 < 1152) {
                int kk = v4 / 18;
                int f  = v4 - kk * 18;
                const float* src = &wk[(size_t)kk * (CIN * 9) + winc + f * 4];
#pragma unroll
                for (int j = 0; j < 4; ++j) {
                    int e = f * 4 + j;
                    int c = e / 9;
                    int q = e - c * 9;
                    cpa4(dWB + (unsigned int)(c * 612 + q * 68 + kk) * 4u, src + j);
                }
            }
        }
    };

    float tot[4][8];
#pragma unroll
    for (int jj = 0; jj < 4; ++jj)
#pragma unroll
        for (int i = 0; i < 8; ++i) tot[jj][i] = 0.f;

    load_chunk(0, 0);
    cp_commit();
    cp_wait0();
    __syncthreads();

    for (int ch = 0; ch < CIN / 8; ++ch) {
        const int cur = ch & 1;
        const bool more = (ch + 1 < CIN / 8);
        if (more) { load_chunk(ch + 1, cur ^ 1); cp_commit(); }

        const float* bIn = sIn + cur * F_IN_TILE;
        const float* bW  = sW  + cur * F_W_TILE + kg * 4;

        float acc[4][8];
#pragma unroll
        for (int jj = 0; jj < 4; ++jj)
#pragma unroll
            for (int i = 0; i < 8; ++i) acc[jj][i] = 0.f;

#pragma unroll
        for (int c = 0; c < 8; ++c) {
            float rows[4][6];
#pragma unroll
            for (int r = 0; r < 4; ++r) {
                const float4 v4 = *(const float4*)&bIn[c * 272 + r * 68 + 4 * pxg];
                const float2 v2 = *(const float2*)&bIn[c * 272 + r * 68 + 4 * pxg + 4];
                rows[r][0] = v4.x; rows[r][1] = v4.y; rows[r][2] = v4.z; rows[r][3] = v4.w;
                rows[r][4] = v2.x; rows[r][5] = v2.y;
            }
#pragma unroll
            for (int dy = 0; dy < 3; ++dy) {
#pragma unroll
                for (int dx = 0; dx < 3; ++dx) {
                    const float4 wq = *(const float4*)&bW[c * 612 + (dy * 3 + dx) * 68];
                    const float wv[4] = {wq.x, wq.y, wq.z, wq.w};
#pragma unroll
                    for (int jj = 0; jj < 4; ++jj)
#pragma unroll
                        for (int ro = 0; ro < 2; ++ro)
#pragma unroll
                            for (int u = 0; u < 4; ++u)
                                acc[jj][ro * 4 + u] =
                                    fmaf(wv[jj], rows[ro + dy][u + dx], acc[jj][ro * 4 + u]);
                }
            }
        }
#pragma unroll
        for (int jj = 0; jj < 4; ++jj)
#pragma unroll
            for (int i = 0; i < 8; ++i) tot[jj][i] += acc[jj][i];

        if (more) cp_wait0();
        __syncthreads();
    }

#pragma unroll
    for (int ro = 0; ro < 2; ++ro) {
        int row = r0 + ro;
#pragma unroll
        for (int u = 0; u < 4; ++u) {
            int col = 4 * pxg + u;
            if (col < WW) {
#pragma unroll
                for (int jj = 0; jj < 4; ++jj) {
                    int k = k0 + kg * 4 + jj;
                    float v = tot[jj][ro * 4 + u] + bias[k];
                    v = fmaxf(v, 0.f);
                    g_feat[((size_t)b * CIN + k) * NPX + row * WW + col] = v;
                }
            }
        }
    }
}

__global__ __launch_bounds__(256, 2) void conv_hybrid_kernel(
    const float* __restrict__ x, const float* __restrict__ w, const float* __restrict__ bias)
{
    extern __shared__ float s[];
    const int bx = blockIdx.x;
    const int group = bx / 296;
    const int pos = bx - group * 296;

    int midx = -1, fidx = -1;
    if (pos < 148) {
        int idx = group * 148 + pos;
        if (idx < MMA_JOBS_TOTAL) midx = idx;
        else                      fidx = FFMA_ELSE_COVER + (idx - MMA_JOBS_TOTAL);  // 732..799
    } else {
        fidx = group * 148 + (pos - 148);                                           // 0..731
    }

    if (midx >= 0) {
        int img = midx / 84;
        int j = midx - img * 84;
        int o0 = (j % 21) * 128;
        int k0 = (j / 21) * 64;
        mma_role(s, w, bias, o0, k0, img);
    } else if (fidx >= 0 && fidx < FMA_JOBS_TOTAL) {
        int img = fidx / 100;
        int r = fidx - img * 100;
        int r0 = (r % 25) * 2;
        int k0 = KSPLIT + (r / 25) * 64;
        ffma_role(s, x, w, bias, r0, k0, img);
    }
}

// ============================================================
// Kernel 2: fused 1x1 heads + anchor decode. (unchanged)
// ============================================================
__global__ __launch_bounds__(256) void heads_decode_kernel(
    const float* __restrict__ wc, const float* __restrict__ bc,
    const float* __restrict__ wr, const float* __restrict__ brg)
{
    extern __shared__ float X[];
    __shared__ float scls[32 * 18];
    __shared__ float sreg[32 * 36];

    const int b = blockIdx.y;
    const int p0 = blockIdx.x * 32;
    const int tid = threadIdx.x;

    for (int idx = tid; idx < CIN * 32; idx += 256) {
        int c = idx >> 5; int j = idx & 31;
        int p = p0 + j;
        X[idx] = (p < NPX) ? g_feat[((size_t)b * CIN + c) * NPX + p] : 0.f;
    }
    __syncthreads();

    for (int t = tid; t < 54 * 8; t += 256) {
        int o = t >> 3;
        int j0 = (t & 7) * 4;
        float bb = (o < 18) ? bc[o] : brg[o - 18];
        const float* W = (o < 18) ? (wc + (size_t)o * CIN) : (wr + (size_t)(o - 18) * CIN);
        float t0 = 0.f, t1 = 0.f, t2 = 0.f, t3 = 0.f;
        for (int cc = 0; cc < CIN; cc += 8) {
            float a0 = 0.f, a1 = 0.f, a2 = 0.f, a3 = 0.f;
#pragma unroll
            for (int u = 0; u < 8; ++u) {
                int c = cc + u;
                float wv = __ldg(&W[c]);
                const float4 xv = *(const float4*)&X[c * 32 + j0];
                a0 = fmaf(wv, xv.x, a0);
                a1 = fmaf(wv, xv.y, a1);
                a2 = fmaf(wv, xv.z, a2);
                a3 = fmaf(wv, xv.w, a3);
            }
            t0 += a0; t1 += a1; t2 += a2; t3 += a3;
        }
        float accs[4] = {t0 + bb, t1 + bb, t2 + bb, t3 + bb};
#pragma unroll
        for (int jj = 0; jj < 4; ++jj) {
            int j = j0 + jj;
            if (o < 18) scls[j * 18 + o] = accs[jj];
            else        sreg[j * 36 + (o - 18)] = accs[jj];
        }
    }
    __syncthreads();

    for (int t = tid; t < 32 * NA; t += 256) {
        int j = t / NA;
        int a = t % NA;
        int p = p0 + j;
        if (p >= NPX) continue;
        int yy = p / WW;
        int xx = p % WW;

        int ri = a / 3, si = a % 3;
        float ratio = (ri == 0) ? 0.5f : (ri == 1 ? 1.0f : 2.0f);
        float scale = (si == 0) ? 8.0f : (si == 1 ? 16.0f : 32.0f);
        float ah = 16.0f * scale * sqrtf(ratio);
        float aw = 16.0f * scale * sqrtf(1.0f / ratio);
        float sy = yy * 16.0f, sx = xx * 16.0f;
        float ay1 = sy + 8.0f - ah * 0.5f;
        float ax1 = sx + 8.0f - aw * 0.5f;
        float ay2 = sy + 8.0f + ah * 0.5f;
        float ax2 = sx + 8.0f + aw * 0.5f;

        float h = ay2 - ay1;
        float w = ax2 - ax1;
        float cy = ay1 + 0.5f * h;
        float cx = ax1 + 0.5f * w;

        const float* rg = &sreg[j * 36 + a * 4];
        float ncy = rg[0] * h + cy;
        float ncx = rg[1] * w + cx;
        float nh = h * expf(rg[2]);
        float nw = w * expf(rg[3]);

        float y1 = fminf(fmaxf(ncy - 0.5f * nh, 0.f), IMGF);
        float x1 = fminf(fmaxf(ncx - 0.5f * nw, 0.f), IMGF);
        float y2 = fminf(fmaxf(ncy + 0.5f * nh, 0.f), IMGF);
        float x2 = fminf(fmaxf(ncx + 0.5f * nw, 0.f), IMGF);

        float hs = y2 - y1, ws = x2 - x1;
        bool valid = (hs >= MIN_SIZE) && (ws >= MIN_SIZE);

        float c0 = scls[j * 18 + a * 2 + 0], c1 = scls[j * 18 + a * 2 + 1];
        float m = fmaxf(c0, c1);
        float e0 = expf(c0 - m);
        float e1 = expf(c1 - m);
        float score = e1 / (e0 + e1);

        int n = p * NA + a;
        float* bx = &g_boxes[((size_t)b * NANCH + n) * 4];
        bx[0] = y1; bx[1] = x1; bx[2] = y2; bx[3] = x2;
        g_key[(size_t)b * NANCH + n] = valid ? (__float_as_uint(score) | 0x80000000u) : 0u;
    }
}

// ============================================================
// Kernel 3: propose (unchanged)
// ============================================================
#define PROP_SMEM 160256

__global__ __launch_bounds__(1024) void propose_kernel(float* __restrict__ out)
{
    extern __shared__ unsigned char smem[];
    unsigned int* skey = (unsigned int*)smem;
    unsigned long long* cand = (unsigned long long*)(smem + 90112);
    float* sb     = (float*)smem;
    float* sarea  = (float*)(smem + 16000);
    float* sscore = (float*)(smem + 20000);
    unsigned int* mask = (unsigned int*)(smem + 24000);
    int* sA = (int*)(smem + 152064);
    int* sB = (int*)(smem + 152064 + 4096);
    __shared__ int s_cnt;
    __shared__ unsigned int s_T;
    __shared__ int s_nc;
    __shared__ int s_NK;
    __shared__ unsigned int kw[32];

    const int b = blockIdx.x;
    const int tid = threadIdx.x;
    const int wid = tid >> 5;
    const int lane = tid & 31;
    const unsigned int* gk = g_key + (size_t)b * NANCH;

    for (int n = tid; n < NANCH; n += 1024) skey[n] = gk[n];
    if (tid == 0) s_T = 0u;
    __syncthreads();

    for (int bit = 31; bit >= 0; --bit) {
        unsigned int T2 = s_T | (1u << bit);
        if (tid == 0) s_cnt = 0;
        __syncthreads();
        int c = 0;
        for (int n = tid; n < NANCH; n += 1024) c += (skey[n] >= T2) ? 1 : 0;
#pragma unroll
        for (int o = 16; o; o >>= 1) c += __shfl_down_sync(0xFFFFFFFFu, c, o);
        if (lane == 0) atomicAdd(&s_cnt, c);
        __syncthreads();
        if (tid == 0 && s_cnt >= PRE_NMS) s_T = T2;
        __syncthreads();
    }
    unsigned int T = s_T;
    if (tid == 0) s_nc = 0;
    __syncthreads();

    for (int n = tid; n < NANCH; n += 1024) {
        unsigned int k = skey[n];
        if (k >= T) {
            int pos = atomicAdd(&s_nc, 1);
            if (pos < 2048)
                cand[pos] = ((unsigned long long)k << 32) | (unsigned int)(~n);
        }
    }
    __syncthreads();
    int nc = min(s_nc, 2048);
    for (int i = tid; i < 2048; i += 1024)
        if (i >= nc) cand[i] = 0ull;
    __syncthreads();

    for (int k = 2; k <= 2048; k <<= 1) {
        for (int j = k >> 1; j > 0; j >>= 1) {
            __syncthreads();
#pragma unroll
            for (int base = 0; base < 2048; base += 1024) {
                int i = base + tid;
                int ixj = i ^ j;
                if (ixj > i) {
                    unsigned long long a = cand[i], c2 = cand[ixj];
                    bool up = ((i & k) == 0);
                    bool swap = up ? (a < c2) : (a > c2);
                    if (swap) { cand[i] = c2; cand[ixj] = a; }
                }
            }
        }
    }
    __syncthreads();

    float myScore = 0.f;
    if (tid < PRE_NMS) {
        unsigned long long ck = cand[tid];
        unsigned int idx = ~(unsigned int)(ck & 0xFFFFFFFFull);
        if (idx >= (unsigned)NANCH) idx = 0;
        const float* bx = g_boxes + ((size_t)b * NANCH + idx) * 4;
        float y1 = bx[0], x1 = bx[1], y2 = bx[2], x2 = bx[3];
        sb[tid * 4 + 0] = y1; sb[tid * 4 + 1] = x1;
        sb[tid * 4 + 2] = y2; sb[tid * 4 + 3] = x2;
        sarea[tid] = (y2 - y1) * (x2 - x1);
        unsigned int kb = (unsigned int)(ck >> 32);
        myScore = __uint_as_float(kb ^ 0x80000000u);
        sscore[tid] = myScore;
    }
    __syncthreads();

    for (int i = wid; i < PRE_NMS; i += 32) {
        const float4 bi = ((const float4*)sb)[i];
        const float ai = sarea[i];
#pragma unroll 4
        for (int w0 = 0; w0 < 32; ++w0) {
            int j = w0 * 32 + lane;
            bool sup = false;
            if (j > i && j < PRE_NMS) {
                const float4 bj = ((const float4*)sb)[j];
                float ty = fmaxf(bi.x, bj.x);
                float tx = fmaxf(bi.y, bj.y);
                float by = fminf(bi.z, bj.z);
                float bxx = fminf(bi.w, bj.w);
                float ih = fmaxf(by - ty, 0.f);
                float iw = fmaxf(bxx - tx, 0.f);
                float inter = ih * iw;
                float iou = inter / (ai + sarea[j] - inter + 1e-9f);
                sup = iou > NMS_THR;
            }
            unsigned int word = __ballot_sync(0xFFFFFFFFu, sup);
            if (lane == 0) mask[i * 32 + w0] = word;
        }
    }
    if (tid < 32) kw[tid] = 0xFFFFFFFFu;
    __syncthreads();

    if (tid < 32) {
        for (int i = 0; i < PRE_NMS; ++i) {
            unsigned int w = kw[i >> 5];
            if ((w >> (i & 31)) & 1u)
                kw[tid] &= ~mask[i * 32 + tid];
            __syncwarp();
        }
    }
    __syncthreads();

    int keepv = (tid < PRE_NMS) ? (int)((kw[tid >> 5] >> (tid & 31)) & 1u) : 0;
    sA[tid] = keepv;
    __syncthreads();
    int* src = sA; int* dst = sB;
    for (int d = 1; d < 1024; d <<= 1) {
        int v = src[tid];
        if (tid >= d) v += src[tid - d];
        dst[tid] = v;
        __syncthreads();
        int* t = src; src = dst; dst = t;
    }
    if (tid == 0) s_NK = src[PRE_NMS - 1];
    __syncthreads();
    int NK = s_NK;

    float* ob = out + (size_t)b * POST_NMS * 5;
    if (tid < PRE_NMS) {
        int incl = src[tid];
        int excl = incl - keepv;
        int slot; float sc;
        if (keepv) { slot = excl; sc = myScore; }
        else       { slot = NK + (tid - excl); sc = -1e30f; }
        if (slot < POST_NMS) {
            ob[slot * 5 + 0] = sb[tid * 4 + 0];
            ob[slot * 5 + 1] = sb[tid * 4 + 1];
            ob[slot * 5 + 2] = sb[tid * 4 + 2];
            ob[slot * 5 + 3] = sb[tid * 4 + 3];
            ob[slot * 5 + 4] = sc;
        }
    }
}

// ============================================================
extern "C" void kernel_launch(void* const* d_in, const int* in_sizes, int n_in,
                              void* d_out, int out_size)
{
    const float* x       = (const float*)d_in[0];
    const float* w_share = (const float*)d_in[1];
    const float* b_share = (const float*)d_in[2];
    const float* w_cls   = (const float*)d_in[3];
    const float* b_cls   = (const float*)d_in[4];
    const float* w_reg   = (const float*)d_in[5];
    const float* b_reg   = (const float*)d_in[6];
    float* out = (float*)d_out;

    cudaFuncSetAttribute(conv_hybrid_kernel, cudaFuncAttributeMaxDynamicSharedMemorySize, HYB_SMEM);
    cudaFuncSetAttribute(heads_decode_kernel, cudaFuncAttributeMaxDynamicSharedMemorySize, CIN * 32 * 4);
    cudaFuncSetAttribute(propose_kernel, cudaFuncAttributeMaxDynamicSharedMemorySize, PROP_SMEM);

    const int prep_total = BATCH * CIN * PFLAT;
    prep_pad_kernel<<<(prep_total + 255) / 256, 256>>>(x);
    conv_hybrid_kernel<<<CONV_BLOCKS, 256, HYB_SMEM>>>(x, w_share, b_share);
    heads_decode_kernel<<<dim3((NPX + 31) / 32, BATCH), 256, CIN * 32 * 4>>>(w_cls, b_cls, w_reg, b_reg);
    propose_kernel<<<BATCH, 1024, PROP_SMEM>>>(out);
}